// round 14
// baseline (speedup 1.0000x reference)
#include <cuda_runtime.h>
#include <cuda_bf16.h>
#include <math.h>

#define NATOM 25600
#define NAA   204800
#define NG    512
#define DD    200
#define HCC   100
#define EATOM 102400
#define EAA   1024000
#define EM2P  512000
#define KPAD  208

#define OUT_ATOM_OFF 0
#define OUT_AA_OFF   (NATOM*DD)
#define OUT_DRUG_OFF (OUT_AA_OFF + NAA*DD)
#define OUT_PROT_OFF (OUT_DRUG_OFF + NG*DD)

#define CDIV(a,b) (((a)+(b)-1)/(b))

typedef unsigned long long ull;

// ---------------- scratch ----------------
__device__ float g_hA[NAA*HCC];
__device__ float g_hB[NAA*HCC];
__device__ float g_hC[NATOM*HCC];
__device__ float g_cat_atom[NATOM*DD];
__device__ float g_cat_aa[NAA*DD];
__device__ float g_atom_h[NATOM*DD];
__device__ float g_wv[16*DD];
__device__ float g_WcA1[200*112];
__device__ float g_WcA2[200*112];
__device__ __nv_bfloat16 g_Xhi[(long)NAA*KPAD];
__device__ __nv_bfloat16 g_Xlo[(long)NAA*KPAD];
__device__ __nv_bfloat16 g_WhT[KPAD*KPAD];
__device__ __nv_bfloat16 g_WlT[KPAD*KPAD];
__device__ float g_dotA[6*NATOM];
__device__ float g_dotP[8*NAA];
__device__ float g_dotH[2*NATOM];
__device__ float g_stats[NG*2];
__device__ float g_ta1[NATOM];
__device__ float g_ta2[NATOM];
__device__ float g_tp1[NAA];
__device__ float g_tp2[NAA];
__device__ float g_sagg[NAA];
__device__ float g_esc[NAA];
__device__ float g_ssum[NG];
__device__ int g_rowptr_a[NATOM+1];
__device__ int g_csrc_a[EATOM+NATOM];
__device__ int g_rowptr_p[NAA+1];
__device__ int g_csrc_p[EAA+NAA];
__device__ int g_rowptr_m[NAA+1];
__device__ int g_csrc_m[EM2P+NATOM];
__device__ int g_deg[NAA];
__device__ int g_part[512];
__device__ int g_goff_a[NG+1];
__device__ int g_goff_p[NG+1];

// ---------------- utils ----------------
__global__ void k_fill_int(int* p, int n, int v){
    int i = blockIdx.x*blockDim.x + threadIdx.x;
    if (i < n) p[i] = v;
}
__global__ void k_fill_f(float* p, int n){
    int i = blockIdx.x*blockDim.x + threadIdx.x;
    if (i < n) p[i] = 0.f;
}
__device__ __forceinline__ float eluf(float v){ return v > 0.f ? v : expm1f(v); }

// ---------------- scans ----------------
__global__ void k_scan_part(const int* __restrict__ deg, int n, int* __restrict__ part){
    __shared__ int sh[512];
    int t = threadIdx.x;
    int i = blockIdx.x*512 + t;
    sh[t] = (i < n) ? deg[i] : 0;
    __syncthreads();
    for (int off = 256; off > 0; off >>= 1){
        if (t < off) sh[t] += sh[t+off];
        __syncthreads();
    }
    if (!t) part[blockIdx.x] = sh[0];
}
__global__ void k_scan_mid(int* part, int nb){
    __shared__ int sh[512];
    int t = threadIdx.x;
    int x0 = (t < nb) ? part[t] : 0;
    sh[t] = x0;
    __syncthreads();
    for (int off = 1; off < 512; off <<= 1){
        int v = (t >= off) ? sh[t-off] : 0;
        __syncthreads();
        sh[t] += v;
        __syncthreads();
    }
    if (t < nb) part[t] = sh[t] - x0;
}
__global__ void k_scan_final(const int* __restrict__ deg, const int* __restrict__ part,
                             int n, int* __restrict__ rowptr, int* __restrict__ cursor){
    __shared__ int sh[512];
    int t = threadIdx.x;
    int i = blockIdx.x*512 + t;
    int x0 = (i < n) ? deg[i] : 0;
    sh[t] = x0;
    __syncthreads();
    for (int off = 1; off < 512; off <<= 1){
        int v = (t >= off) ? sh[t-off] : 0;
        __syncthreads();
        sh[t] += v;
        __syncthreads();
    }
    if (i < n){
        int inc = sh[t] + part[blockIdx.x];
        rowptr[i+1] = inc;
        cursor[i] = inc - x0;
    }
    if (i == 0) rowptr[0] = 0;
}
__global__ void k_scan512(const int* __restrict__ deg, int* __restrict__ off){
    __shared__ int sh[NG];
    int t = threadIdx.x;
    sh[t] = deg[t];
    __syncthreads();
    for (int o = 1; o < NG; o <<= 1){
        int v = (t >= o) ? sh[t-o] : 0;
        __syncthreads();
        sh[t] += v;
        __syncthreads();
    }
    off[t+1] = sh[t];
    if (!t) off[0] = 0;
}

// ---------------- CSR build ----------------
__global__ void k_deg(const int* __restrict__ dst, int E, int nloop, int* __restrict__ deg){
    int i = blockIdx.x*blockDim.x + threadIdx.x;
    int tot = E + nloop;
    if (i >= tot) return;
    int d = (i < E) ? dst[i] : (i - E);
    atomicAdd(&deg[d], 1);
}
__global__ void k_fill_csr(const int* __restrict__ src, const int* __restrict__ dst,
                           int E, int nloop,
                           int* __restrict__ cursor, int* __restrict__ csrc){
    int i = blockIdx.x*blockDim.x + threadIdx.x;
    int tot = E + nloop;
    if (i >= tot) return;
    int d, v;
    if (i < E){ d = dst[i]; v = src[i]; }
    else      { d = i - E;  v = d | 0x80000000; }
    int pos = atomicAdd(&cursor[d], 1);
    csrc[pos] = v;
}

// ---------------- w-tilde ----------------
__global__ void k_wtilde(const float* __restrict__ Wd, const float* __restrict__ ad_src,
                         const float* __restrict__ ad_dst,
                         const float* __restrict__ Wp, const float* __restrict__ ap_src,
                         const float* __restrict__ ap_dst,
                         const float* __restrict__ Wi_src, const float* __restrict__ ai_src,
                         const float* __restrict__ Wi_dst, const float* __restrict__ ai_dst,
                         float* __restrict__ wv){
    int d = threadIdx.x;
    if (d >= DD) return;
    const float* Ws[16]  = {Wd,Wd,Wd,Wd, Wi_dst,Wi_dst, Wi_src,Wi_src, Wp,Wp, Wp,Wp, Wi_dst,Wi_dst, Wi_src,Wi_src};
    const float* as[16]  = {ad_src,ad_src,ad_dst,ad_dst, ai_dst,ai_dst, ai_src,ai_src,
                            ap_src,ap_src, ap_dst,ap_dst, ai_dst,ai_dst, ai_src,ai_src};
    const int    hs[16]  = {0,1,0,1, 0,1, 0,1, 0,1, 0,1, 0,1, 0,1};
    for (int slot = 0; slot < 16; slot++){
        const float* W = Ws[slot]; const float* a = as[slot]; int h = hs[slot];
        float s = 0.f;
        for (int c = 0; c < 50; c++) s += W[d*HCC + h*50 + c]*a[h*50 + c];
        wv[slot*DD + d] = s;
    }
}

// ---------------- combined weights + transposed bf16 split W ----------------
__global__ void k_prepW2(const float* __restrict__ Wd, const float* __restrict__ Wp,
                         const float* __restrict__ Wi_src, const float* __restrict__ wv,
                         float* __restrict__ WcA1, float* __restrict__ WcA2,
                         __nv_bfloat16* __restrict__ WhT, __nv_bfloat16* __restrict__ WlT){
    int i = blockIdx.x*blockDim.x + threadIdx.x;
    const int S1 = 200*112;
    if (i < S1){
        int k = i/112, c = i%112;
        float v = 0.f;
        if (c < 100) v = Wd[k*HCC + c];
        else if (c < 106) v = wv[(c-100)*DD + k];
        WcA1[i] = v;
    } else if (i < 2*S1){
        int j = i - S1; int k = j/112, c = j%112;
        float v = 0.f;
        if (c < 100) v = Wi_src[k*HCC + c];
        else if (c < 102) v = wv[(14 + (c-100))*DD + k];
        WcA2[j] = v;
    } else if (i < 2*S1 + KPAD*KPAD){
        int j = i - 2*S1; int n = j / KPAD, k = j % KPAD;
        float v = 0.f;
        if (k < 200){
            if (n < 100) v = Wi_src[k*HCC + n];
            else if (n < 200) v = Wp[k*HCC + (n-100)];
            else v = wv[(6 + (n-200))*DD + k];
        }
        __nv_bfloat16 h = __float2bfloat16(v);
        float hv = __bfloat162float(h);
        WhT[j] = h;
        WlT[j] = __float2bfloat16(v - hv);
    }
}

// ---------------- X conversion: elu + bf16 split, vectorized (4 cols/thread) ----------------
__global__ void k_cvt_x4(const float* __restrict__ x,
                         ull* __restrict__ hi, ull* __restrict__ lo){
    long i = (long)blockIdx.x*blockDim.x + threadIdx.x;
    long tot = (long)NAA*(KPAD/4);
    if (i >= tot) return;
    int q = (int)(i % (KPAD/4));
    long row = i / (KPAD/4);
    int col = q*4;
    float4 v = make_float4(0.f,0.f,0.f,0.f);
    if (col < 200) v = *(const float4*)(x + row*DD + col);
    v.x = eluf(v.x); v.y = eluf(v.y); v.z = eluf(v.z); v.w = eluf(v.w);
    __nv_bfloat162 h01 = __floats2bfloat162_rn(v.x, v.y);
    __nv_bfloat162 h23 = __floats2bfloat162_rn(v.z, v.w);
    float2 f01 = __bfloat1622float2(h01);
    float2 f23 = __bfloat1622float2(h23);
    __nv_bfloat162 l01 = __floats2bfloat162_rn(v.x - f01.x, v.y - f01.y);
    __nv_bfloat162 l23 = __floats2bfloat162_rn(v.z - f23.x, v.w - f23.y);
    unsigned hu0 = *(unsigned*)&h01, hu1 = *(unsigned*)&h23;
    unsigned lu0 = *(unsigned*)&l01, lu1 = *(unsigned*)&l23;
    hi[i] = ((ull)hu1 << 32) | hu0;
    lo[i] = ((ull)lu1 << 32) | lu0;
}

// ---------------- HMMA dual GEMM v3: BM=64, 2 blocks/SM, double-buffered ----------------
#define AP 24
#define SMA (64*AP)          /* 1536 bf16 per A buffer */
#define SMB (208*AP)         /* 4992 bf16 per B buffer */
#define SM_BYTES ((4*SMA + 4*SMB)*2)

#define MMA16816(d, a, b0, b1) \
    asm volatile("mma.sync.aligned.m16n8k16.row.col.f32.bf16.bf16.f32 " \
        "{%0,%1,%2,%3}, {%4,%5,%6,%7}, {%8,%9}, {%0,%1,%2,%3};" \
        : "+f"((d)[0]),"+f"((d)[1]),"+f"((d)[2]),"+f"((d)[3]) \
        : "r"((a)[0]),"r"((a)[1]),"r"((a)[2]),"r"((a)[3]), "r"(b0),"r"(b1))

__global__ __launch_bounds__(256,2)
void k_hmma(const __nv_bfloat16* __restrict__ Xhi, const __nv_bfloat16* __restrict__ Xlo,
            const __nv_bfloat16* __restrict__ Bhg, const __nv_bfloat16* __restrict__ Blg,
            float* __restrict__ O0, float* __restrict__ O1,
            float* __restrict__ dots, int twoN){
    extern __shared__ __nv_bfloat16 sm[];
    __nv_bfloat16* AhB = sm;                 // [2][SMA]
    __nv_bfloat16* AlB = sm + 2*SMA;
    __nv_bfloat16* BhB = sm + 4*SMA;         // [2][SMB]
    __nv_bfloat16* BlB = sm + 4*SMA + 2*SMB;
    int tid = threadIdx.x;
    int wid = tid >> 5, lane = tid & 31;
    int wm = wid & 3, wn = wid >> 2;
    int g = lane >> 2, tig = lane & 3;
    long row0 = (long)blockIdx.x * 64;

    // A fill coords: 512 items / 256 thr = 2 each
    int ar0 = tid >> 3,            akp0 = tid & 7;
    int ar1 = (tid + 256) >> 3,    akp1 = (tid + 256) & 7;
    // B fill coords: 1664 items / 256 = 6.5 -> 7 slots
    int br[7], bkp[7];
    #pragma unroll
    for (int i = 0; i < 7; i++){ int u = tid + i*256; br[i] = u >> 3; bkp[i] = u & 7; }

    float acc[13][4];
    #pragma unroll
    for (int j = 0; j < 13; j++)
        #pragma unroll
        for (int q = 0; q < 4; q++) acc[j][q] = 0.f;

    unsigned pah[2], pal[2], pbh[7], pbl[7];

    // prefetch chunk 0
    pah[0] = *(const unsigned*)(Xhi + (row0 + ar0)*KPAD + akp0*2);
    pal[0] = *(const unsigned*)(Xlo + (row0 + ar0)*KPAD + akp0*2);
    pah[1] = *(const unsigned*)(Xhi + (row0 + ar1)*KPAD + akp1*2);
    pal[1] = *(const unsigned*)(Xlo + (row0 + ar1)*KPAD + akp1*2);
    #pragma unroll
    for (int i = 0; i < 7; i++){
        if (tid + i*256 < 1664){
            pbh[i] = *(const unsigned*)(Bhg + (long)br[i]*KPAD + bkp[i]*2);
            pbl[i] = *(const unsigned*)(Blg + (long)br[i]*KPAD + bkp[i]*2);
        }
    }
    // commit chunk 0 to buffer 0
    *(unsigned*)&AhB[ar0*AP + akp0*2] = pah[0];
    *(unsigned*)&AlB[ar0*AP + akp0*2] = pal[0];
    *(unsigned*)&AhB[ar1*AP + akp1*2] = pah[1];
    *(unsigned*)&AlB[ar1*AP + akp1*2] = pal[1];
    #pragma unroll
    for (int i = 0; i < 7; i++){
        if (tid + i*256 < 1664){
            *(unsigned*)&BhB[br[i]*AP + bkp[i]*2] = pbh[i];
            *(unsigned*)&BlB[br[i]*AP + bkp[i]*2] = pbl[i];
        }
    }
    __syncthreads();

    for (int kc = 0; kc < 13; kc++){
        int cur = kc & 1;
        if (kc < 12){
            int k0 = (kc+1)*16;
            pah[0] = *(const unsigned*)(Xhi + (row0 + ar0)*KPAD + k0 + akp0*2);
            pal[0] = *(const unsigned*)(Xlo + (row0 + ar0)*KPAD + k0 + akp0*2);
            pah[1] = *(const unsigned*)(Xhi + (row0 + ar1)*KPAD + k0 + akp1*2);
            pal[1] = *(const unsigned*)(Xlo + (row0 + ar1)*KPAD + k0 + akp1*2);
            #pragma unroll
            for (int i = 0; i < 7; i++){
                if (tid + i*256 < 1664){
                    pbh[i] = *(const unsigned*)(Bhg + (long)br[i]*KPAD + k0 + bkp[i]*2);
                    pbl[i] = *(const unsigned*)(Blg + (long)br[i]*KPAD + k0 + bkp[i]*2);
                }
            }
        }
        const __nv_bfloat16* Ah = AhB + cur*SMA;
        const __nv_bfloat16* Al = AlB + cur*SMA;
        const __nv_bfloat16* Bh = BhB + cur*SMB;
        const __nv_bfloat16* Bl = BlB + cur*SMB;
        int ab = (wm*16 + g)*AP + tig*2;
        unsigned ah[4], al[4];
        ah[0] = *(const unsigned*)&Ah[ab];
        ah[1] = *(const unsigned*)&Ah[ab + 8*AP];
        ah[2] = *(const unsigned*)&Ah[ab + 8];
        ah[3] = *(const unsigned*)&Ah[ab + 8*AP + 8];
        al[0] = *(const unsigned*)&Al[ab];
        al[1] = *(const unsigned*)&Al[ab + 8*AP];
        al[2] = *(const unsigned*)&Al[ab + 8];
        al[3] = *(const unsigned*)&Al[ab + 8*AP + 8];
        #pragma unroll
        for (int j = 0; j < 13; j++){
            int bb = (wn*104 + j*8 + g)*AP + tig*2;
            unsigned bh0 = *(const unsigned*)&Bh[bb];
            unsigned bh1 = *(const unsigned*)&Bh[bb + 8];
            unsigned bl0 = *(const unsigned*)&Bl[bb];
            unsigned bl1 = *(const unsigned*)&Bl[bb + 8];
            MMA16816(acc[j], ah, bh0, bh1);
            MMA16816(acc[j], ah, bl0, bl1);
            MMA16816(acc[j], al, bh0, bh1);
        }
        if (kc < 12){
            int nxt = cur ^ 1;
            *(unsigned*)&AhB[nxt*SMA + ar0*AP + akp0*2] = pah[0];
            *(unsigned*)&AlB[nxt*SMA + ar0*AP + akp0*2] = pal[0];
            *(unsigned*)&AhB[nxt*SMA + ar1*AP + akp1*2] = pah[1];
            *(unsigned*)&AlB[nxt*SMA + ar1*AP + akp1*2] = pal[1];
            #pragma unroll
            for (int i = 0; i < 7; i++){
                if (tid + i*256 < 1664){
                    *(unsigned*)&BhB[nxt*SMB + br[i]*AP + bkp[i]*2] = pbh[i];
                    *(unsigned*)&BlB[nxt*SMB + br[i]*AP + bkp[i]*2] = pbl[i];
                }
            }
        }
        __syncthreads();
    }

    // epilogue: float2 stores, route cols to hA / hB / dots
    long r_hi = row0 + wm*16 + g;
    long r_lo = r_hi + 8;
    #pragma unroll
    for (int j = 0; j < 13; j++){
        int colb = wn*104 + j*8 + tig*2;
        #pragma unroll
        for (int h = 0; h < 2; h++){
            long row = h ? r_lo : r_hi;
            float2 v = make_float2(acc[j][2*h], acc[j][2*h+1]);
            if (colb < 100)      *(float2*)&O0[row*HCC + colb] = v;
            else if (colb < 200) *(float2*)&O1[row*HCC + (colb-100)] = v;
            else {
                int pr = (colb - 200) >> 1;
                *(float2*)&dots[(long)pr*twoN + row*2] = v;
            }
        }
    }
}

// ---------------- GEMM v6 (fp32 FMA2, atom-side) ----------------
#define FMA2(acc, x, w) asm("fma.rn.f32x2 %0, %1, %2, %0;" : "+l"(acc) : "l"(x), "l"(w))
#define DUP2(dst, f)    asm("mov.b64 %0, {%1, %1};" : "=l"(dst) : "r"(__float_as_uint(f)))

template<int NW, int NOUT, int NDOT, bool ELU>
__global__ __launch_bounds__(NW*32, 2)
void k_gemm6(const float* __restrict__ X, const float* __restrict__ Wc,
             float* __restrict__ O0, float* __restrict__ O1,
             float* __restrict__ dots, int twoN){
    constexpr int NC = NW*16;
    constexpr int T  = NW*32;
    constexpr int NXF = (320 + T - 1)/T;
    constexpr int NWF = (20*NC + T - 1)/T;
    __shared__ __align__(16) float Xs[20][64];
    __shared__ __align__(16) float Ws[20*NC];
    int tid = threadIdx.x;
    int wi = tid >> 5, lane = tid & 31;
    long row0 = (long)blockIdx.x * 64;

    float4 xv[NXF];
    float wreg[NWF];

    #pragma unroll
    for (int i = 0; i < NXF; i++){
        int u = tid + i*T;
        if (u < 320){
            int r = u/5, q = u%5;
            float4 v = *(const float4*)&X[(row0+r)*DD + q*4];
            if (ELU){ v.x=eluf(v.x); v.y=eluf(v.y); v.z=eluf(v.z); v.w=eluf(v.w); }
            xv[i] = v;
        }
    }
    #pragma unroll
    for (int i = 0; i < NWF; i++){
        int u = tid + i*T;
        if (u < 20*NC) wreg[i] = Wc[u];
    }

    ull acc[2][8];
    #pragma unroll
    for (int r = 0; r < 2; r++)
        #pragma unroll
        for (int j = 0; j < 8; j++) acc[r][j] = 0ull;

    for (int it = 0; it < 10; it++){
        if (it) __syncthreads();
        #pragma unroll
        for (int i = 0; i < NXF; i++){
            int u = tid + i*T;
            if (u < 320){
                int r = u/5, q = u%5;
                #pragma unroll
                for (int j = 0; j < 4; j++)
                    Xs[q*4+j][r] = ((const float*)&xv[i])[j];
            }
        }
        #pragma unroll
        for (int i = 0; i < NWF; i++){
            int u = tid + i*T;
            if (u < 20*NC) Ws[u] = wreg[i];
        }
        __syncthreads();
        if (it < 9){
            int k0n = (it+1)*20;
            #pragma unroll
            for (int i = 0; i < NXF; i++){
                int u = tid + i*T;
                if (u < 320){
                    int r = u/5, q = u%5;
                    float4 v = *(const float4*)&X[(row0+r)*DD + k0n + q*4];
                    if (ELU){ v.x=eluf(v.x); v.y=eluf(v.y); v.z=eluf(v.z); v.w=eluf(v.w); }
                    xv[i] = v;
                }
            }
            #pragma unroll
            for (int i = 0; i < NWF; i++){
                int u = tid + i*T;
                if (u < 20*NC) wreg[i] = Wc[k0n*NC + u];
            }
        }
        #pragma unroll 5
        for (int k = 0; k < 20; k++){
            float2 x2 = *(const float2*)&Xs[k][2*lane];
            ull xlo, xhi;
            DUP2(xlo, x2.x);
            DUP2(xhi, x2.y);
            const ulonglong2* wp = (const ulonglong2*)&Ws[k*NC + wi*16];
            ulonglong2 wA = wp[0], wB = wp[1], wC = wp[2], wD = wp[3];
            ull wc8[8] = {wA.x, wA.y, wB.x, wB.y, wC.x, wC.y, wD.x, wD.y};
            #pragma unroll
            for (int j = 0; j < 8; j++){
                FMA2(acc[0][j], xlo, wc8[j]);
                FMA2(acc[1][j], xhi, wc8[j]);
            }
        }
    }

    #pragma unroll
    for (int j = 0; j < 8; j++){
        int col = wi*16 + 2*j;
        long r0 = row0 + 2*lane;
        if (col < 100){
            *(ull*)&O0[r0*HCC + col]     = acc[0][j];
            *(ull*)&O0[(r0+1)*HCC + col] = acc[1][j];
        } else if (NOUT == 2 && col < 200){
            *(ull*)&O1[r0*HCC + (col-100)]     = acc[0][j];
            *(ull*)&O1[(r0+1)*HCC + (col-100)] = acc[1][j];
        } else if (col >= 100*NOUT && col < 100*NOUT + NDOT){
            int pr = (col - 100*NOUT) >> 1;
            *(ull*)&dots[(long)pr*twoN + r0*2]     = acc[0][j];
            *(ull*)&dots[(long)pr*twoN + (r0+1)*2] = acc[1][j];
        }
    }
}

// ---------------- fused GAT aggregation + LN stats ----------------
__global__ void k_gat_node(const int* __restrict__ rowptr, const int* __restrict__ csrc,
                           const float* __restrict__ hs,
                           const float* __restrict__ als, const float* __restrict__ ald,
                           const float* __restrict__ bias, const int* __restrict__ batch,
                           float* __restrict__ stats,
                           float* __restrict__ out, int coloff, int n){
    int w = (blockIdx.x*blockDim.x + threadIdx.x) >> 5;
    int lane = threadIdx.x & 31;
    if (w >= n) return;
    float ald0 = ald[2*w], ald1 = ald[2*w+1];
    int beg = rowptr[w], end = rowptr[w+1];
    float a0 = 0.f, a1 = 0.f, a2 = 0.f, a3 = 0.f, z0 = 0.f, z1 = 0.f;
    for (int j = beg; j < end; j++){
        int s = csrc[j] & 0x7fffffff;
        float l0 = als[2*s]   + ald0;
        float l1 = als[2*s+1] + ald1;
        l0 = l0 > 0.f ? l0 : 0.2f*l0;
        l1 = l1 > 0.f ? l1 : 0.2f*l1;
        float e0 = expf(l0), e1 = expf(l1);
        z0 += e0; z1 += e1;
        const float* h = hs + (long)s*HCC;
        a0 += e0*h[lane];
        a1 += (lane < 18 ? e0 : e1) * h[lane+32];
        a2 += e1*h[lane+64];
        if (lane < 4) a3 += e1*h[lane+96];
    }
    float iz0 = 1.f/(z0 + 1e-16f), iz1 = 1.f/(z1 + 1e-16f);
    float o0 = bias[lane]    + a0*iz0;
    float o1 = bias[lane+32] + a1*(lane < 18 ? iz0 : iz1);
    float o2 = bias[lane+64] + a2*iz1;
    float o3 = (lane < 4) ? (bias[lane+96] + a3*iz1) : 0.f;
    float* o = out + (long)w*DD + coloff;
    o[lane]    = o0;
    o[lane+32] = o1;
    o[lane+64] = o2;
    if (lane < 4) o[lane+96] = o3;
    float s  = o0 + o1 + o2 + o3;
    float s2 = o0*o0 + o1*o1 + o2*o2 + o3*o3;
    #pragma unroll
    for (int off = 16; off > 0; off >>= 1){
        s  += __shfl_down_sync(0xffffffffu, s,  off);
        s2 += __shfl_down_sync(0xffffffffu, s2, off);
    }
    if (!lane){
        int b = batch[w];
        atomicAdd(&stats[2*b],   s);
        atomicAdd(&stats[2*b+1], s2);
    }
}

// ---------------- warp-per-row LN apply + ELU + fused SAG dots ----------------
__global__ void k_ln_pool(const float* __restrict__ x, const int* __restrict__ batch,
                          const int* __restrict__ goff, const float* __restrict__ stats,
                          const float* __restrict__ w, const float* __restrict__ bia,
                          const float* __restrict__ wrel, const float* __restrict__ wroot,
                          float* __restrict__ y, float* __restrict__ t1,
                          float* __restrict__ t2, int n){
    __shared__ float sw[DD], sb[DD], sr[DD], so[DD];
    for (int i = threadIdx.x; i < DD; i += blockDim.x){
        sw[i] = w[i]; sb[i] = bia[i]; sr[i] = wrel[i]; so[i] = wroot[i];
    }
    __syncthreads();
    int row = (blockIdx.x*blockDim.x + threadIdx.x) >> 5;
    int lane = threadIdx.x & 31;
    if (row >= n) return;
    int b = batch[row];
    float cnt = (float)(goff[b+1] - goff[b]);
    float norm = fmaxf(cnt, 1.f) * (float)DD;
    float mean = stats[2*b] / norm;
    float var  = stats[2*b+1] / norm - mean*mean;
    float rs   = rsqrtf(fmaxf(var, 0.f) + 1e-5f);
    const float* xr = x + (long)row*DD;
    float* yr = y + (long)row*DD;
    float a = 0.f, bb = 0.f;
    #pragma unroll
    for (int c = lane; c < DD; c += 32){
        float v = eluf((xr[c] - mean)*rs*sw[c] + sb[c]);
        yr[c] = v;
        a  += v*sr[c];
        bb += v*so[c];
    }
    #pragma unroll
    for (int off = 16; off > 0; off >>= 1){
        a  += __shfl_down_sync(0xffffffffu, a,  off);
        bb += __shfl_down_sync(0xffffffffu, bb, off);
    }
    if (!lane){ t1[row] = a; t2[row] = bb; }
}

// ---------------- SAG pooling ----------------
__global__ void k_sagg_csr(const int* __restrict__ rowptr, const int* __restrict__ csrc,
                           const float* __restrict__ t1, float* __restrict__ sagg, int n){
    int i = blockIdx.x*blockDim.x + threadIdx.x;
    if (i >= n) return;
    float s = 0.f;
    int beg = rowptr[i], end = rowptr[i+1];
    for (int j = beg; j < end; j++){
        int v = csrc[j];
        if (v >= 0) s += t1[v];
    }
    sagg[i] = s;
}
__global__ void k_score_g(const float* __restrict__ sagg, const float* __restrict__ t2,
                          const float* __restrict__ brel, const int* __restrict__ goff,
                          float* __restrict__ e, float* __restrict__ ssum){
    int g = blockIdx.x;
    int beg = goff[g], end = goff[g+1];
    int t = threadIdx.x;
    float b0 = brel[0];
    __shared__ float red[256];
    float m = -3.4e38f;
    for (int r = beg + t; r < end; r += 256)
        m = fmaxf(m, sagg[r] + b0 + t2[r]);
    red[t] = m;
    __syncthreads();
    for (int off = 128; off > 0; off >>= 1){
        if (t < off) red[t] = fmaxf(red[t], red[t+off]);
        __syncthreads();
    }
    m = red[0];
    __syncthreads();
    float s = 0.f;
    for (int r = beg + t; r < end; r += 256){
        float v = expf(sagg[r] + b0 + t2[r] - m);
        e[r] = v; s += v;
    }
    red[t] = s;
    __syncthreads();
    for (int off = 128; off > 0; off >>= 1){
        if (t < off) red[t] += red[t+off];
        __syncthreads();
    }
    if (!t) ssum[g] = red[0];
}
__global__ void k_final_chunk(const float* __restrict__ x, const int* __restrict__ batch,
                              const float* __restrict__ e, const float* __restrict__ ssum,
                              float* __restrict__ out, float* __restrict__ gsum, int n){
    int c = threadIdx.x;
    int r0 = blockIdx.x*64;
    int r1 = min(r0 + 64, n);
    int gcur = batch[r0];
    float inv = 1.f/(ssum[gcur] + 1e-16f);
    float acc = 0.f;
    for (int r = r0; r < r1; r++){
        int g = batch[r];
        if (g != gcur){
            atomicAdd(&gsum[gcur*DD + c], acc);
            acc = 0.f; gcur = g;
            inv = 1.f/(ssum[g] + 1e-16f);
        }
        float sc = e[r]*inv;
        float v = x[(long)r*DD + c]*sc;
        out[(long)r*DD + c] = v;
        acc += v;
    }
    atomicAdd(&gsum[gcur*DD + c], acc);
}

// ---------------- host ----------------
static void* symaddr(const void* s){ void* p = nullptr; cudaGetSymbolAddress(&p, s); return p; }

static void build_csr(const int* src, const int* dst, int E, int nloop, int n,
                      int* deg, int* part, int* rowptr, int* csrc){
    int nb = CDIV(n, 512);
    k_fill_int<<<CDIV(n,256),256>>>(deg, n, 0);
    k_deg<<<CDIV(E+nloop,256),256>>>(dst, E, nloop, deg);
    k_scan_part<<<nb,512>>>(deg, n, part);
    k_scan_mid<<<1,512>>>(part, nb);
    k_scan_final<<<nb,512>>>(deg, part, n, rowptr, deg);
    k_fill_csr<<<CDIV(E+nloop,256),256>>>(src, dst, E, nloop, deg, csrc);
}

extern "C" void kernel_launch(void* const* d_in, const int* in_sizes, int n_in,
                              void* d_out, int out_size){
    const float* atom_x    = (const float*)d_in[0];
    const int*   atom_ei   = (const int*)  d_in[1];
    const int*   atom_batch= (const int*)  d_in[2];
    const float* aa_x      = (const float*)d_in[3];
    const int*   aa_ei     = (const int*)  d_in[4];
    const int*   aa_batch  = (const int*)  d_in[6];
    const int*   m2p       = (const int*)  d_in[7];
    const float* Wd     = (const float*)d_in[8];
    const float* ad_src = (const float*)d_in[9];
    const float* ad_dst = (const float*)d_in[10];
    const float* bd     = (const float*)d_in[11];
    const float* Wp     = (const float*)d_in[12];
    const float* ap_src = (const float*)d_in[13];
    const float* ap_dst = (const float*)d_in[14];
    const float* bp     = (const float*)d_in[15];
    const float* Wi_src = (const float*)d_in[16];
    const float* Wi_dst = (const float*)d_in[17];
    const float* ai_src = (const float*)d_in[18];
    const float* ai_dst = (const float*)d_in[19];
    const float* bi     = (const float*)d_in[20];
    const float* ln_d_w = (const float*)d_in[21];
    const float* ln_d_b = (const float*)d_in[22];
    const float* ln_p_w = (const float*)d_in[23];
    const float* ln_p_b = (const float*)d_in[24];
    const float* pd_Wrel  = (const float*)d_in[25];
    const float* pd_brel  = (const float*)d_in[26];
    const float* pd_Wroot = (const float*)d_in[27];
    const float* pp_Wrel  = (const float*)d_in[28];
    const float* pp_brel  = (const float*)d_in[29];
    const float* pp_Wroot = (const float*)d_in[30];

    float* hA     = (float*)symaddr(g_hA);
    float* hB     = (float*)symaddr(g_hB);
    float* hC     = (float*)symaddr(g_hC);
    float* cat_a  = (float*)symaddr(g_cat_atom);
    float* cat_p  = (float*)symaddr(g_cat_aa);
    float* atom_h = (float*)symaddr(g_atom_h);
    float* wv     = (float*)symaddr(g_wv);
    float* WcA1   = (float*)symaddr(g_WcA1);
    float* WcA2   = (float*)symaddr(g_WcA2);
    __nv_bfloat16* Xhi = (__nv_bfloat16*)symaddr(g_Xhi);
    __nv_bfloat16* Xlo = (__nv_bfloat16*)symaddr(g_Xlo);
    __nv_bfloat16* WhT = (__nv_bfloat16*)symaddr(g_WhT);
    __nv_bfloat16* WlT = (__nv_bfloat16*)symaddr(g_WlT);
    float* dotA   = (float*)symaddr(g_dotA);
    float* dotP   = (float*)symaddr(g_dotP);
    float* dotH   = (float*)symaddr(g_dotH);
    float* stats  = (float*)symaddr(g_stats);
    float* ta1    = (float*)symaddr(g_ta1);
    float* ta2    = (float*)symaddr(g_ta2);
    float* tp1    = (float*)symaddr(g_tp1);
    float* tp2    = (float*)symaddr(g_tp2);
    float* sagg   = (float*)symaddr(g_sagg);
    float* esc    = (float*)symaddr(g_esc);
    float* ssum   = (float*)symaddr(g_ssum);
    int* rowptr_a = (int*)symaddr(g_rowptr_a);
    int* csrc_a   = (int*)symaddr(g_csrc_a);
    int* rowptr_p = (int*)symaddr(g_rowptr_p);
    int* csrc_p   = (int*)symaddr(g_csrc_p);
    int* rowptr_m = (int*)symaddr(g_rowptr_m);
    int* csrc_m   = (int*)symaddr(g_csrc_m);
    int* deg      = (int*)symaddr(g_deg);
    int* part     = (int*)symaddr(g_part);
    int* goff_a   = (int*)symaddr(g_goff_a);
    int* goff_p   = (int*)symaddr(g_goff_p);

    float* out      = (float*)d_out;
    float* out_atom = out + OUT_ATOM_OFF;
    float* out_aa   = out + OUT_AA_OFF;
    float* out_drug = out + OUT_DRUG_OFF;
    float* out_prot = out + OUT_PROT_OFF;

    const int BS = 256;
    const int* atom_src = atom_ei;  const int* atom_dst = atom_ei + EATOM;
    const int* aa_src   = aa_ei;    const int* aa_dst   = aa_ei + EAA;
    const int* m2p_at   = m2p;      const int* m2p_aa   = m2p + EM2P;

    cudaFuncSetAttribute(k_hmma, cudaFuncAttributeMaxDynamicSharedMemorySize, SM_BYTES);

    // 0: w-tilde, 1: weights, 2: X conversion
    k_wtilde<<<1,224>>>(Wd, ad_src, ad_dst, Wp, ap_src, ap_dst,
                        Wi_src, ai_src, Wi_dst, ai_dst, wv);
    k_prepW2<<<CDIV(2*200*112 + KPAD*KPAD, BS),BS>>>(Wd, Wp, Wi_src, wv, WcA1, WcA2, WhT, WlT);
    k_cvt_x4<<<CDIV((long)NAA*(KPAD/4), BS),BS>>>(aa_x, (ull*)Xhi, (ull*)Xlo);
    // 3: HMMA dual GEMM (ncu slot 3)
    k_hmma<<<NAA/64, 256, SM_BYTES>>>(Xhi, Xlo, WhT, WlT, hA, hB, dotP, 2*NAA);
    // 4: atom layer-1 GEMM (+6 dot cols)
    k_gemm6<7,1,6,true><<<NATOM/64,224>>>(atom_x, WcA1, hC, nullptr, dotA, 2*NATOM);

    // graph offsets
    k_fill_int<<<CDIV(NG,BS),BS>>>(deg, NG, 0);
    k_deg<<<CDIV(NATOM,BS),BS>>>(atom_batch, NATOM, 0, deg);
    k_scan512<<<1,NG>>>(deg, goff_a);
    k_fill_int<<<CDIV(NG,BS),BS>>>(deg, NG, 0);
    k_deg<<<CDIV(NAA,BS),BS>>>(aa_batch, NAA, 0, deg);
    k_scan512<<<1,NG>>>(deg, goff_p);

    // CSR builds
    build_csr(atom_src, atom_dst, EATOM, NATOM, NATOM, deg, part, rowptr_a, csrc_a);
    build_csr(aa_src,   aa_dst,   EAA,   NAA,   NAA,   deg, part, rowptr_p, csrc_p);
    build_csr(m2p_aa,   m2p_at,   EM2P,  NATOM, NATOM, deg, part, rowptr_m, csrc_m);

    // GAT1 + GAT2 + fused LN stats -> cat_a
    k_fill_f<<<CDIV(NG*2,BS),BS>>>(stats, NG*2);
    k_gat_node<<<CDIV(NATOM*32,BS),BS>>>(rowptr_a, csrc_a, hC,
                                         dotA, dotA + 2*NATOM, bd, atom_batch, stats, cat_a, 0, NATOM);
    k_gat_node<<<CDIV(NATOM*32,BS),BS>>>(rowptr_m, csrc_m, hA,
                                         dotP, dotA + 4*NATOM, bi, atom_batch, stats, cat_a, HCC, NATOM);
    k_ln_pool<<<CDIV(NATOM*32,BS),BS>>>(cat_a, atom_batch, goff_a, stats,
                                        ln_d_w, ln_d_b, pd_Wrel, pd_Wroot,
                                        atom_h, ta1, ta2, NATOM);

    // layer 2
    k_gemm6<7,1,2,false><<<NATOM/64,224>>>(atom_h, WcA2, hC, nullptr, dotH, 2*NATOM);
    build_csr(m2p_at, m2p_aa, EM2P, NATOM, NAA, deg, part, rowptr_m, csrc_m);

    k_fill_f<<<CDIV(NG*2,BS),BS>>>(stats, NG*2);
    k_gat_node<<<CDIV(NAA*32,BS),BS>>>(rowptr_p, csrc_p, hB,
                                       dotP + 2*NAA, dotP + 4*NAA, bp, aa_batch, stats, cat_p, 0, NAA);
    k_gat_node<<<CDIV(NAA*32,BS),BS>>>(rowptr_m, csrc_m, hC,
                                       dotH, dotP + 6*NAA, bi, aa_batch, stats, cat_p, HCC, NAA);
    k_ln_pool<<<CDIV(NAA*32,BS),BS>>>(cat_p, aa_batch, goff_p, stats,
                                      ln_p_w, ln_p_b, pp_Wrel, pp_Wroot,
                                      out_aa, tp1, tp2, NAA);

    // SAG pool (atoms) + drug_g
    k_sagg_csr<<<CDIV(NATOM,BS),BS>>>(rowptr_a, csrc_a, ta1, sagg, NATOM);
    k_score_g<<<NG,256>>>(sagg, ta2, pd_brel, goff_a, esc, ssum);
    k_fill_f<<<CDIV(NG*DD,BS),BS>>>(out_drug, NG*DD);
    k_final_chunk<<<CDIV(NATOM,64),DD>>>(atom_h, atom_batch, esc, ssum, out_atom, out_drug, NATOM);

    // SAG pool (aa) + prot_g
    k_sagg_csr<<<CDIV(NAA,BS),BS>>>(rowptr_p, csrc_p, tp1, sagg, NAA);
    k_score_g<<<NG,256>>>(sagg, tp2, pp_brel, goff_p, esc, ssum);
    k_fill_f<<<CDIV(NG*DD,BS),BS>>>(out_prot, NG*DD);
    k_final_chunk<<<CDIV(NAA,64),DD>>>(out_aa, aa_batch, esc, ssum, out_aa, out_prot, NAA);
}

// round 15
// speedup vs baseline: 1.3198x; 1.3198x over previous
#include <cuda_runtime.h>
#include <cuda_bf16.h>
#include <math.h>

#define NATOM 25600
#define NAA   204800
#define NG    512
#define DD    200
#define HCC   100
#define EATOM 102400
#define EAA   1024000
#define EM2P  512000
#define KPAD  208

#define OUT_ATOM_OFF 0
#define OUT_AA_OFF   (NATOM*DD)
#define OUT_DRUG_OFF (OUT_AA_OFF + NAA*DD)
#define OUT_PROT_OFF (OUT_DRUG_OFF + NG*DD)

#define CDIV(a,b) (((a)+(b)-1)/(b))

typedef unsigned long long ull;

// ---------------- scratch ----------------
__device__ float g_hA[NAA*HCC];
__device__ float g_hB[NAA*HCC];
__device__ float g_hC[NATOM*HCC];
__device__ float g_cat_atom[NATOM*DD];
__device__ float g_cat_aa[NAA*DD];
__device__ float g_atom_h[NATOM*DD];
__device__ float g_wv[16*DD];
__device__ float g_WcA1[200*112];
__device__ float g_WcA2[200*112];
__device__ __nv_bfloat16 g_Xhi[(long)NAA*KPAD];
__device__ __nv_bfloat16 g_Xlo[(long)NAA*KPAD];
__device__ __nv_bfloat16 g_WhT[KPAD*KPAD];
__device__ __nv_bfloat16 g_WlT[KPAD*KPAD];
__device__ float g_dotA[6*NATOM];
__device__ float g_dotP[8*NAA];
__device__ float g_dotH[2*NATOM];
__device__ float g_stats[NG*2];
__device__ float g_ta1[NATOM];
__device__ float g_ta2[NATOM];
__device__ float g_tp1[NAA];
__device__ float g_tp2[NAA];
__device__ float g_sagg[NAA];
__device__ float g_esc[NAA];
__device__ float g_ssum[NG];
__device__ int g_rowptr_a[NATOM+1];
__device__ int g_csrc_a[EATOM+NATOM];
__device__ int g_rowptr_p[NAA+1];
__device__ int g_csrc_p[EAA+NAA];
__device__ int g_rowptr_m[NAA+1];
__device__ int g_csrc_m[EM2P+NATOM];
__device__ int g_deg[NAA];
__device__ int g_part[512];
__device__ int g_goff_a[NG+1];
__device__ int g_goff_p[NG+1];

// ---------------- utils ----------------
__global__ void k_fill_int(int* p, int n, int v){
    int i = blockIdx.x*blockDim.x + threadIdx.x;
    if (i < n) p[i] = v;
}
__global__ void k_fill_f(float* p, int n){
    int i = blockIdx.x*blockDim.x + threadIdx.x;
    if (i < n) p[i] = 0.f;
}
__device__ __forceinline__ float eluf(float v){ return v > 0.f ? v : expm1f(v); }

// ---------------- scans ----------------
__global__ void k_scan_part(const int* __restrict__ deg, int n, int* __restrict__ part){
    __shared__ int sh[512];
    int t = threadIdx.x;
    int i = blockIdx.x*512 + t;
    sh[t] = (i < n) ? deg[i] : 0;
    __syncthreads();
    for (int off = 256; off > 0; off >>= 1){
        if (t < off) sh[t] += sh[t+off];
        __syncthreads();
    }
    if (!t) part[blockIdx.x] = sh[0];
}
__global__ void k_scan_mid(int* part, int nb){
    __shared__ int sh[512];
    int t = threadIdx.x;
    int x0 = (t < nb) ? part[t] : 0;
    sh[t] = x0;
    __syncthreads();
    for (int off = 1; off < 512; off <<= 1){
        int v = (t >= off) ? sh[t-off] : 0;
        __syncthreads();
        sh[t] += v;
        __syncthreads();
    }
    if (t < nb) part[t] = sh[t] - x0;
}
__global__ void k_scan_final(const int* __restrict__ deg, const int* __restrict__ part,
                             int n, int* __restrict__ rowptr, int* __restrict__ cursor){
    __shared__ int sh[512];
    int t = threadIdx.x;
    int i = blockIdx.x*512 + t;
    int x0 = (i < n) ? deg[i] : 0;
    sh[t] = x0;
    __syncthreads();
    for (int off = 1; off < 512; off <<= 1){
        int v = (t >= off) ? sh[t-off] : 0;
        __syncthreads();
        sh[t] += v;
        __syncthreads();
    }
    if (i < n){
        int inc = sh[t] + part[blockIdx.x];
        rowptr[i+1] = inc;
        cursor[i] = inc - x0;
    }
    if (i == 0) rowptr[0] = 0;
}
__global__ void k_scan512(const int* __restrict__ deg, int* __restrict__ off){
    __shared__ int sh[NG];
    int t = threadIdx.x;
    sh[t] = deg[t];
    __syncthreads();
    for (int o = 1; o < NG; o <<= 1){
        int v = (t >= o) ? sh[t-o] : 0;
        __syncthreads();
        sh[t] += v;
        __syncthreads();
    }
    off[t+1] = sh[t];
    if (!t) off[0] = 0;
}

// ---------------- CSR build ----------------
__global__ void k_deg(const int* __restrict__ dst, int E, int nloop, int* __restrict__ deg){
    int i = blockIdx.x*blockDim.x + threadIdx.x;
    int tot = E + nloop;
    if (i >= tot) return;
    int d = (i < E) ? dst[i] : (i - E);
    atomicAdd(&deg[d], 1);
}
__global__ void k_fill_csr(const int* __restrict__ src, const int* __restrict__ dst,
                           int E, int nloop,
                           int* __restrict__ cursor, int* __restrict__ csrc){
    int i = blockIdx.x*blockDim.x + threadIdx.x;
    int tot = E + nloop;
    if (i >= tot) return;
    int d, v;
    if (i < E){ d = dst[i]; v = src[i]; }
    else      { d = i - E;  v = d | 0x80000000; }
    int pos = atomicAdd(&cursor[d], 1);
    csrc[pos] = v;
}

// ---------------- w-tilde ----------------
__global__ void k_wtilde(const float* __restrict__ Wd, const float* __restrict__ ad_src,
                         const float* __restrict__ ad_dst,
                         const float* __restrict__ Wp, const float* __restrict__ ap_src,
                         const float* __restrict__ ap_dst,
                         const float* __restrict__ Wi_src, const float* __restrict__ ai_src,
                         const float* __restrict__ Wi_dst, const float* __restrict__ ai_dst,
                         float* __restrict__ wv){
    int d = threadIdx.x;
    if (d >= DD) return;
    const float* Ws[16]  = {Wd,Wd,Wd,Wd, Wi_dst,Wi_dst, Wi_src,Wi_src, Wp,Wp, Wp,Wp, Wi_dst,Wi_dst, Wi_src,Wi_src};
    const float* as[16]  = {ad_src,ad_src,ad_dst,ad_dst, ai_dst,ai_dst, ai_src,ai_src,
                            ap_src,ap_src, ap_dst,ap_dst, ai_dst,ai_dst, ai_src,ai_src};
    const int    hs[16]  = {0,1,0,1, 0,1, 0,1, 0,1, 0,1, 0,1, 0,1};
    for (int slot = 0; slot < 16; slot++){
        const float* W = Ws[slot]; const float* a = as[slot]; int h = hs[slot];
        float s = 0.f;
        for (int c = 0; c < 50; c++) s += W[d*HCC + h*50 + c]*a[h*50 + c];
        wv[slot*DD + d] = s;
    }
}

// ---------------- combined weights + transposed bf16 split W ----------------
__global__ void k_prepW2(const float* __restrict__ Wd, const float* __restrict__ Wp,
                         const float* __restrict__ Wi_src, const float* __restrict__ wv,
                         float* __restrict__ WcA1, float* __restrict__ WcA2,
                         __nv_bfloat16* __restrict__ WhT, __nv_bfloat16* __restrict__ WlT){
    int i = blockIdx.x*blockDim.x + threadIdx.x;
    const int S1 = 200*112;
    if (i < S1){
        int k = i/112, c = i%112;
        float v = 0.f;
        if (c < 100) v = Wd[k*HCC + c];
        else if (c < 106) v = wv[(c-100)*DD + k];
        WcA1[i] = v;
    } else if (i < 2*S1){
        int j = i - S1; int k = j/112, c = j%112;
        float v = 0.f;
        if (c < 100) v = Wi_src[k*HCC + c];
        else if (c < 102) v = wv[(14 + (c-100))*DD + k];
        WcA2[j] = v;
    } else if (i < 2*S1 + KPAD*KPAD){
        int j = i - 2*S1; int n = j / KPAD, k = j % KPAD;
        float v = 0.f;
        if (k < 200){
            if (n < 100) v = Wi_src[k*HCC + n];
            else if (n < 200) v = Wp[k*HCC + (n-100)];
            else v = wv[(6 + (n-200))*DD + k];
        }
        __nv_bfloat16 h = __float2bfloat16(v);
        float hv = __bfloat162float(h);
        WhT[j] = h;
        WlT[j] = __float2bfloat16(v - hv);
    }
}

// ---------------- X conversion: elu + bf16 split, K padded to 208 ----------------
__global__ void k_cvt_x(const float* __restrict__ x,
                        __nv_bfloat16* __restrict__ hi, __nv_bfloat16* __restrict__ lo){
    long i = (long)blockIdx.x*blockDim.x + threadIdx.x;
    long tot = (long)NAA*KPAD;
    if (i >= tot) return;
    int col = (int)(i % KPAD);
    long row = i / KPAD;
    float v = 0.f;
    if (col < 200) v = eluf(x[row*DD + col]);
    __nv_bfloat16 h = __float2bfloat16(v);
    float hv = __bfloat162float(h);
    hi[i] = h;
    lo[i] = __float2bfloat16(v - hv);
}

// ---------------- HMMA dual GEMM v4: W smem-resident, barrier-free mainloop ----------------
#define WPITCH 216
#define SM_BYTES (2*KPAD*WPITCH*2)   /* Wh + Wl, bf16 */

#define MMA16816(d, a, b0, b1) \
    asm volatile("mma.sync.aligned.m16n8k16.row.col.f32.bf16.bf16.f32 " \
        "{%0,%1,%2,%3}, {%4,%5,%6,%7}, {%8,%9}, {%0,%1,%2,%3};" \
        : "+f"((d)[0]),"+f"((d)[1]),"+f"((d)[2]),"+f"((d)[3]) \
        : "r"((a)[0]),"r"((a)[1]),"r"((a)[2]),"r"((a)[3]), "r"(b0),"r"(b1))

__global__ __launch_bounds__(512,1)
void k_hmma(const __nv_bfloat16* __restrict__ Xhi, const __nv_bfloat16* __restrict__ Xlo,
            const __nv_bfloat16* __restrict__ Bhg, const __nv_bfloat16* __restrict__ Blg,
            float* __restrict__ O0, float* __restrict__ O1,
            float* __restrict__ dots, int twoN){
    extern __shared__ __nv_bfloat16 sm[];
    __nv_bfloat16* Wh = sm;
    __nv_bfloat16* Wl = sm + KPAD*WPITCH;
    int tid = threadIdx.x;
    int wid = tid >> 5, lane = tid & 31;
    int wm = wid & 7, wn = wid >> 3;
    int g = lane >> 2, tig = lane & 3;
    long row0 = (long)blockIdx.x * 128;

    // one-time W load (coalesced 4B chunks)
    for (int u = tid; u < KPAD*104; u += 512){
        int n = u / 104, kp = u % 104;
        *(unsigned*)&Wh[n*WPITCH + kp*2] = *(const unsigned*)(Bhg + (long)n*KPAD + kp*2);
        *(unsigned*)&Wl[n*WPITCH + kp*2] = *(const unsigned*)(Blg + (long)n*KPAD + kp*2);
    }
    __syncthreads();

    float acc[13][4];
    #pragma unroll
    for (int j = 0; j < 13; j++)
        #pragma unroll
        for (int q = 0; q < 4; q++) acc[j][q] = 0.f;

    long ar0 = (row0 + wm*16 + g)*KPAD + tig*2;
    long ar8 = ar0 + 8*KPAD;

    unsigned ah[4], al[4], pah[4], pal[4];
    // prefetch chunk 0
    pah[0] = *(const unsigned*)(Xhi + ar0);
    pah[1] = *(const unsigned*)(Xhi + ar8);
    pah[2] = *(const unsigned*)(Xhi + ar0 + 8);
    pah[3] = *(const unsigned*)(Xhi + ar8 + 8);
    pal[0] = *(const unsigned*)(Xlo + ar0);
    pal[1] = *(const unsigned*)(Xlo + ar8);
    pal[2] = *(const unsigned*)(Xlo + ar0 + 8);
    pal[3] = *(const unsigned*)(Xlo + ar8 + 8);

    for (int kc = 0; kc < 13; kc++){
        #pragma unroll
        for (int q = 0; q < 4; q++){ ah[q] = pah[q]; al[q] = pal[q]; }
        if (kc < 12){
            int k0 = (kc+1)*16;
            pah[0] = *(const unsigned*)(Xhi + ar0 + k0);
            pah[1] = *(const unsigned*)(Xhi + ar8 + k0);
            pah[2] = *(const unsigned*)(Xhi + ar0 + k0 + 8);
            pah[3] = *(const unsigned*)(Xhi + ar8 + k0 + 8);
            pal[0] = *(const unsigned*)(Xlo + ar0 + k0);
            pal[1] = *(const unsigned*)(Xlo + ar8 + k0);
            pal[2] = *(const unsigned*)(Xlo + ar0 + k0 + 8);
            pal[3] = *(const unsigned*)(Xlo + ar8 + k0 + 8);
        }
        int kb = kc*16 + tig*2;
        #pragma unroll
        for (int j = 0; j < 13; j++){
            int nrow = wn*104 + j*8 + g;
            const __nv_bfloat16* wph = &Wh[nrow*WPITCH + kb];
            const __nv_bfloat16* wpl = &Wl[nrow*WPITCH + kb];
            unsigned bh0 = *(const unsigned*)wph;
            unsigned bh1 = *(const unsigned*)(wph + 8);
            unsigned bl0 = *(const unsigned*)wpl;
            unsigned bl1 = *(const unsigned*)(wpl + 8);
            MMA16816(acc[j], ah, bh0, bh1);
            MMA16816(acc[j], ah, bl0, bl1);
            MMA16816(acc[j], al, bh0, bh1);
        }
    }

    // epilogue: float2 stores, route cols to hA / hB / dots
    long r_hi = row0 + wm*16 + g;
    long r_lo = r_hi + 8;
    #pragma unroll
    for (int j = 0; j < 13; j++){
        int colb = wn*104 + j*8 + tig*2;
        #pragma unroll
        for (int h = 0; h < 2; h++){
            long row = h ? r_lo : r_hi;
            float2 v = make_float2(acc[j][2*h], acc[j][2*h+1]);
            if (colb < 100)      *(float2*)&O0[row*HCC + colb] = v;
            else if (colb < 200) *(float2*)&O1[row*HCC + (colb-100)] = v;
            else {
                int pr = (colb - 200) >> 1;
                *(float2*)&dots[(long)pr*twoN + row*2] = v;
            }
        }
    }
}

// ---------------- GEMM v6 (fp32 FMA2, atom-side) ----------------
#define FMA2(acc, x, w) asm("fma.rn.f32x2 %0, %1, %2, %0;" : "+l"(acc) : "l"(x), "l"(w))
#define DUP2(dst, f)    asm("mov.b64 %0, {%1, %1};" : "=l"(dst) : "r"(__float_as_uint(f)))

template<int NW, int NOUT, int NDOT, bool ELU>
__global__ __launch_bounds__(NW*32, 2)
void k_gemm6(const float* __restrict__ X, const float* __restrict__ Wc,
             float* __restrict__ O0, float* __restrict__ O1,
             float* __restrict__ dots, int twoN){
    constexpr int NC = NW*16;
    constexpr int T  = NW*32;
    constexpr int NXF = (320 + T - 1)/T;
    constexpr int NWF = (20*NC + T - 1)/T;
    __shared__ __align__(16) float Xs[20][64];
    __shared__ __align__(16) float Ws[20*NC];
    int tid = threadIdx.x;
    int wi = tid >> 5, lane = tid & 31;
    long row0 = (long)blockIdx.x * 64;

    float4 xv[NXF];
    float wreg[NWF];

    #pragma unroll
    for (int i = 0; i < NXF; i++){
        int u = tid + i*T;
        if (u < 320){
            int r = u/5, q = u%5;
            float4 v = *(const float4*)&X[(row0+r)*DD + q*4];
            if (ELU){ v.x=eluf(v.x); v.y=eluf(v.y); v.z=eluf(v.z); v.w=eluf(v.w); }
            xv[i] = v;
        }
    }
    #pragma unroll
    for (int i = 0; i < NWF; i++){
        int u = tid + i*T;
        if (u < 20*NC) wreg[i] = Wc[u];
    }

    ull acc[2][8];
    #pragma unroll
    for (int r = 0; r < 2; r++)
        #pragma unroll
        for (int j = 0; j < 8; j++) acc[r][j] = 0ull;

    for (int it = 0; it < 10; it++){
        if (it) __syncthreads();
        #pragma unroll
        for (int i = 0; i < NXF; i++){
            int u = tid + i*T;
            if (u < 320){
                int r = u/5, q = u%5;
                #pragma unroll
                for (int j = 0; j < 4; j++)
                    Xs[q*4+j][r] = ((const float*)&xv[i])[j];
            }
        }
        #pragma unroll
        for (int i = 0; i < NWF; i++){
            int u = tid + i*T;
            if (u < 20*NC) Ws[u] = wreg[i];
        }
        __syncthreads();
        if (it < 9){
            int k0n = (it+1)*20;
            #pragma unroll
            for (int i = 0; i < NXF; i++){
                int u = tid + i*T;
                if (u < 320){
                    int r = u/5, q = u%5;
                    float4 v = *(const float4*)&X[(row0+r)*DD + k0n + q*4];
                    if (ELU){ v.x=eluf(v.x); v.y=eluf(v.y); v.z=eluf(v.z); v.w=eluf(v.w); }
                    xv[i] = v;
                }
            }
            #pragma unroll
            for (int i = 0; i < NWF; i++){
                int u = tid + i*T;
                if (u < 20*NC) wreg[i] = Wc[k0n*NC + u];
            }
        }
        #pragma unroll 5
        for (int k = 0; k < 20; k++){
            float2 x2 = *(const float2*)&Xs[k][2*lane];
            ull xlo, xhi;
            DUP2(xlo, x2.x);
            DUP2(xhi, x2.y);
            const ulonglong2* wp = (const ulonglong2*)&Ws[k*NC + wi*16];
            ulonglong2 wA = wp[0], wB = wp[1], wC = wp[2], wD = wp[3];
            ull wc8[8] = {wA.x, wA.y, wB.x, wB.y, wC.x, wC.y, wD.x, wD.y};
            #pragma unroll
            for (int j = 0; j < 8; j++){
                FMA2(acc[0][j], xlo, wc8[j]);
                FMA2(acc[1][j], xhi, wc8[j]);
            }
        }
    }

    #pragma unroll
    for (int j = 0; j < 8; j++){
        int col = wi*16 + 2*j;
        long r0 = row0 + 2*lane;
        if (col < 100){
            *(ull*)&O0[r0*HCC + col]     = acc[0][j];
            *(ull*)&O0[(r0+1)*HCC + col] = acc[1][j];
        } else if (NOUT == 2 && col < 200){
            *(ull*)&O1[r0*HCC + (col-100)]     = acc[0][j];
            *(ull*)&O1[(r0+1)*HCC + (col-100)] = acc[1][j];
        } else if (col >= 100*NOUT && col < 100*NOUT + NDOT){
            int pr = (col - 100*NOUT) >> 1;
            *(ull*)&dots[(long)pr*twoN + r0*2]     = acc[0][j];
            *(ull*)&dots[(long)pr*twoN + (r0+1)*2] = acc[1][j];
        }
    }
}

// ---------------- fused GAT aggregation + LN stats ----------------
__global__ void k_gat_node(const int* __restrict__ rowptr, const int* __restrict__ csrc,
                           const float* __restrict__ hs,
                           const float* __restrict__ als, const float* __restrict__ ald,
                           const float* __restrict__ bias, const int* __restrict__ batch,
                           float* __restrict__ stats,
                           float* __restrict__ out, int coloff, int n){
    int w = (blockIdx.x*blockDim.x + threadIdx.x) >> 5;
    int lane = threadIdx.x & 31;
    if (w >= n) return;
    float ald0 = ald[2*w], ald1 = ald[2*w+1];
    int beg = rowptr[w], end = rowptr[w+1];
    float a0 = 0.f, a1 = 0.f, a2 = 0.f, a3 = 0.f, z0 = 0.f, z1 = 0.f;
    for (int j = beg; j < end; j++){
        int s = csrc[j] & 0x7fffffff;
        float l0 = als[2*s]   + ald0;
        float l1 = als[2*s+1] + ald1;
        l0 = l0 > 0.f ? l0 : 0.2f*l0;
        l1 = l1 > 0.f ? l1 : 0.2f*l1;
        float e0 = expf(l0), e1 = expf(l1);
        z0 += e0; z1 += e1;
        const float* h = hs + (long)s*HCC;
        a0 += e0*h[lane];
        a1 += (lane < 18 ? e0 : e1) * h[lane+32];
        a2 += e1*h[lane+64];
        if (lane < 4) a3 += e1*h[lane+96];
    }
    float iz0 = 1.f/(z0 + 1e-16f), iz1 = 1.f/(z1 + 1e-16f);
    float o0 = bias[lane]    + a0*iz0;
    float o1 = bias[lane+32] + a1*(lane < 18 ? iz0 : iz1);
    float o2 = bias[lane+64] + a2*iz1;
    float o3 = (lane < 4) ? (bias[lane+96] + a3*iz1) : 0.f;
    float* o = out + (long)w*DD + coloff;
    o[lane]    = o0;
    o[lane+32] = o1;
    o[lane+64] = o2;
    if (lane < 4) o[lane+96] = o3;
    float s  = o0 + o1 + o2 + o3;
    float s2 = o0*o0 + o1*o1 + o2*o2 + o3*o3;
    #pragma unroll
    for (int off = 16; off > 0; off >>= 1){
        s  += __shfl_down_sync(0xffffffffu, s,  off);
        s2 += __shfl_down_sync(0xffffffffu, s2, off);
    }
    if (!lane){
        int b = batch[w];
        atomicAdd(&stats[2*b],   s);
        atomicAdd(&stats[2*b+1], s2);
    }
}

// ---------------- warp-per-row LN apply + ELU + fused SAG dots ----------------
__global__ void k_ln_pool(const float* __restrict__ x, const int* __restrict__ batch,
                          const int* __restrict__ goff, const float* __restrict__ stats,
                          const float* __restrict__ w, const float* __restrict__ bia,
                          const float* __restrict__ wrel, const float* __restrict__ wroot,
                          float* __restrict__ y, float* __restrict__ t1,
                          float* __restrict__ t2, int n){
    __shared__ float sw[DD], sb[DD], sr[DD], so[DD];
    for (int i = threadIdx.x; i < DD; i += blockDim.x){
        sw[i] = w[i]; sb[i] = bia[i]; sr[i] = wrel[i]; so[i] = wroot[i];
    }
    __syncthreads();
    int row = (blockIdx.x*blockDim.x + threadIdx.x) >> 5;
    int lane = threadIdx.x & 31;
    if (row >= n) return;
    int b = batch[row];
    float cnt = (float)(goff[b+1] - goff[b]);
    float norm = fmaxf(cnt, 1.f) * (float)DD;
    float mean = stats[2*b] / norm;
    float var  = stats[2*b+1] / norm - mean*mean;
    float rs   = rsqrtf(fmaxf(var, 0.f) + 1e-5f);
    const float* xr = x + (long)row*DD;
    float* yr = y + (long)row*DD;
    float a = 0.f, bb = 0.f;
    #pragma unroll
    for (int c = lane; c < DD; c += 32){
        float v = eluf((xr[c] - mean)*rs*sw[c] + sb[c]);
        yr[c] = v;
        a  += v*sr[c];
        bb += v*so[c];
    }
    #pragma unroll
    for (int off = 16; off > 0; off >>= 1){
        a  += __shfl_down_sync(0xffffffffu, a,  off);
        bb += __shfl_down_sync(0xffffffffu, bb, off);
    }
    if (!lane){ t1[row] = a; t2[row] = bb; }
}

// ---------------- SAG pooling ----------------
__global__ void k_sagg_csr(const int* __restrict__ rowptr, const int* __restrict__ csrc,
                           const float* __restrict__ t1, float* __restrict__ sagg, int n){
    int i = blockIdx.x*blockDim.x + threadIdx.x;
    if (i >= n) return;
    float s = 0.f;
    int beg = rowptr[i], end = rowptr[i+1];
    for (int j = beg; j < end; j++){
        int v = csrc[j];
        if (v >= 0) s += t1[v];
    }
    sagg[i] = s;
}
__global__ void k_score_g(const float* __restrict__ sagg, const float* __restrict__ t2,
                          const float* __restrict__ brel, const int* __restrict__ goff,
                          float* __restrict__ e, float* __restrict__ ssum){
    int g = blockIdx.x;
    int beg = goff[g], end = goff[g+1];
    int t = threadIdx.x;
    float b0 = brel[0];
    __shared__ float red[256];
    float m = -3.4e38f;
    for (int r = beg + t; r < end; r += 256)
        m = fmaxf(m, sagg[r] + b0 + t2[r]);
    red[t] = m;
    __syncthreads();
    for (int off = 128; off > 0; off >>= 1){
        if (t < off) red[t] = fmaxf(red[t], red[t+off]);
        __syncthreads();
    }
    m = red[0];
    __syncthreads();
    float s = 0.f;
    for (int r = beg + t; r < end; r += 256){
        float v = expf(sagg[r] + b0 + t2[r] - m);
        e[r] = v; s += v;
    }
    red[t] = s;
    __syncthreads();
    for (int off = 128; off > 0; off >>= 1){
        if (t < off) red[t] += red[t+off];
        __syncthreads();
    }
    if (!t) ssum[g] = red[0];
}
__global__ void k_final_chunk(const float* __restrict__ x, const int* __restrict__ batch,
                              const float* __restrict__ e, const float* __restrict__ ssum,
                              float* __restrict__ out, float* __restrict__ gsum, int n){
    int c = threadIdx.x;
    int r0 = blockIdx.x*64;
    int r1 = min(r0 + 64, n);
    int gcur = batch[r0];
    float inv = 1.f/(ssum[gcur] + 1e-16f);
    float acc = 0.f;
    for (int r = r0; r < r1; r++){
        int g = batch[r];
        if (g != gcur){
            atomicAdd(&gsum[gcur*DD + c], acc);
            acc = 0.f; gcur = g;
            inv = 1.f/(ssum[g] + 1e-16f);
        }
        float sc = e[r]*inv;
        float v = x[(long)r*DD + c]*sc;
        out[(long)r*DD + c] = v;
        acc += v;
    }
    atomicAdd(&gsum[gcur*DD + c], acc);
}

// ---------------- host ----------------
static void* symaddr(const void* s){ void* p = nullptr; cudaGetSymbolAddress(&p, s); return p; }

static void build_csr(const int* src, const int* dst, int E, int nloop, int n,
                      int* deg, int* part, int* rowptr, int* csrc){
    int nb = CDIV(n, 512);
    k_fill_int<<<CDIV(n,256),256>>>(deg, n, 0);
    k_deg<<<CDIV(E+nloop,256),256>>>(dst, E, nloop, deg);
    k_scan_part<<<nb,512>>>(deg, n, part);
    k_scan_mid<<<1,512>>>(part, nb);
    k_scan_final<<<nb,512>>>(deg, part, n, rowptr, deg);
    k_fill_csr<<<CDIV(E+nloop,256),256>>>(src, dst, E, nloop, deg, csrc);
}

extern "C" void kernel_launch(void* const* d_in, const int* in_sizes, int n_in,
                              void* d_out, int out_size){
    const float* atom_x    = (const float*)d_in[0];
    const int*   atom_ei   = (const int*)  d_in[1];
    const int*   atom_batch= (const int*)  d_in[2];
    const float* aa_x      = (const float*)d_in[3];
    const int*   aa_ei     = (const int*)  d_in[4];
    const int*   aa_batch  = (const int*)  d_in[6];
    const int*   m2p       = (const int*)  d_in[7];
    const float* Wd     = (const float*)d_in[8];
    const float* ad_src = (const float*)d_in[9];
    const float* ad_dst = (const float*)d_in[10];
    const float* bd     = (const float*)d_in[11];
    const float* Wp     = (const float*)d_in[12];
    const float* ap_src = (const float*)d_in[13];
    const float* ap_dst = (const float*)d_in[14];
    const float* bp     = (const float*)d_in[15];
    const float* Wi_src = (const float*)d_in[16];
    const float* Wi_dst = (const float*)d_in[17];
    const float* ai_src = (const float*)d_in[18];
    const float* ai_dst = (const float*)d_in[19];
    const float* bi     = (const float*)d_in[20];
    const float* ln_d_w = (const float*)d_in[21];
    const float* ln_d_b = (const float*)d_in[22];
    const float* ln_p_w = (const float*)d_in[23];
    const float* ln_p_b = (const float*)d_in[24];
    const float* pd_Wrel  = (const float*)d_in[25];
    const float* pd_brel  = (const float*)d_in[26];
    const float* pd_Wroot = (const float*)d_in[27];
    const float* pp_Wrel  = (const float*)d_in[28];
    const float* pp_brel  = (const float*)d_in[29];
    const float* pp_Wroot = (const float*)d_in[30];

    float* hA     = (float*)symaddr(g_hA);
    float* hB     = (float*)symaddr(g_hB);
    float* hC     = (float*)symaddr(g_hC);
    float* cat_a  = (float*)symaddr(g_cat_atom);
    float* cat_p  = (float*)symaddr(g_cat_aa);
    float* atom_h = (float*)symaddr(g_atom_h);
    float* wv     = (float*)symaddr(g_wv);
    float* WcA1   = (float*)symaddr(g_WcA1);
    float* WcA2   = (float*)symaddr(g_WcA2);
    __nv_bfloat16* Xhi = (__nv_bfloat16*)symaddr(g_Xhi);
    __nv_bfloat16* Xlo = (__nv_bfloat16*)symaddr(g_Xlo);
    __nv_bfloat16* WhT = (__nv_bfloat16*)symaddr(g_WhT);
    __nv_bfloat16* WlT = (__nv_bfloat16*)symaddr(g_WlT);
    float* dotA   = (float*)symaddr(g_dotA);
    float* dotP   = (float*)symaddr(g_dotP);
    float* dotH   = (float*)symaddr(g_dotH);
    float* stats  = (float*)symaddr(g_stats);
    float* ta1    = (float*)symaddr(g_ta1);
    float* ta2    = (float*)symaddr(g_ta2);
    float* tp1    = (float*)symaddr(g_tp1);
    float* tp2    = (float*)symaddr(g_tp2);
    float* sagg   = (float*)symaddr(g_sagg);
    float* esc    = (float*)symaddr(g_esc);
    float* ssum   = (float*)symaddr(g_ssum);
    int* rowptr_a = (int*)symaddr(g_rowptr_a);
    int* csrc_a   = (int*)symaddr(g_csrc_a);
    int* rowptr_p = (int*)symaddr(g_rowptr_p);
    int* csrc_p   = (int*)symaddr(g_csrc_p);
    int* rowptr_m = (int*)symaddr(g_rowptr_m);
    int* csrc_m   = (int*)symaddr(g_csrc_m);
    int* deg      = (int*)symaddr(g_deg);
    int* part     = (int*)symaddr(g_part);
    int* goff_a   = (int*)symaddr(g_goff_a);
    int* goff_p   = (int*)symaddr(g_goff_p);

    float* out      = (float*)d_out;
    float* out_atom = out + OUT_ATOM_OFF;
    float* out_aa   = out + OUT_AA_OFF;
    float* out_drug = out + OUT_DRUG_OFF;
    float* out_prot = out + OUT_PROT_OFF;

    const int BS = 256;
    const int* atom_src = atom_ei;  const int* atom_dst = atom_ei + EATOM;
    const int* aa_src   = aa_ei;    const int* aa_dst   = aa_ei + EAA;
    const int* m2p_at   = m2p;      const int* m2p_aa   = m2p + EM2P;

    cudaFuncSetAttribute(k_hmma, cudaFuncAttributeMaxDynamicSharedMemorySize, SM_BYTES);

    // 0: w-tilde, 1: weights, 2: X conversion
    k_wtilde<<<1,224>>>(Wd, ad_src, ad_dst, Wp, ap_src, ap_dst,
                        Wi_src, ai_src, Wi_dst, ai_dst, wv);
    k_prepW2<<<CDIV(2*200*112 + KPAD*KPAD, BS),BS>>>(Wd, Wp, Wi_src, wv, WcA1, WcA2, WhT, WlT);
    k_cvt_x<<<CDIV((long)NAA*KPAD, BS),BS>>>(aa_x, Xhi, Xlo);
    // 3: HMMA dual GEMM (ncu slot 3)
    k_hmma<<<NAA/128, 512, SM_BYTES>>>(Xhi, Xlo, WhT, WlT, hA, hB, dotP, 2*NAA);
    // 4: atom layer-1 GEMM (+6 dot cols)
    k_gemm6<7,1,6,true><<<NATOM/64,224>>>(atom_x, WcA1, hC, nullptr, dotA, 2*NATOM);

    // graph offsets
    k_fill_int<<<CDIV(NG,BS),BS>>>(deg, NG, 0);
    k_deg<<<CDIV(NATOM,BS),BS>>>(atom_batch, NATOM, 0, deg);
    k_scan512<<<1,NG>>>(deg, goff_a);
    k_fill_int<<<CDIV(NG,BS),BS>>>(deg, NG, 0);
    k_deg<<<CDIV(NAA,BS),BS>>>(aa_batch, NAA, 0, deg);
    k_scan512<<<1,NG>>>(deg, goff_p);

    // CSR builds
    build_csr(atom_src, atom_dst, EATOM, NATOM, NATOM, deg, part, rowptr_a, csrc_a);
    build_csr(aa_src,   aa_dst,   EAA,   NAA,   NAA,   deg, part, rowptr_p, csrc_p);
    build_csr(m2p_aa,   m2p_at,   EM2P,  NATOM, NATOM, deg, part, rowptr_m, csrc_m);

    // GAT1 + GAT2 + fused LN stats -> cat_a
    k_fill_f<<<CDIV(NG*2,BS),BS>>>(stats, NG*2);
    k_gat_node<<<CDIV(NATOM*32,BS),BS>>>(rowptr_a, csrc_a, hC,
                                         dotA, dotA + 2*NATOM, bd, atom_batch, stats, cat_a, 0, NATOM);
    k_gat_node<<<CDIV(NATOM*32,BS),BS>>>(rowptr_m, csrc_m, hA,
                                         dotP, dotA + 4*NATOM, bi, atom_batch, stats, cat_a, HCC, NATOM);
    k_ln_pool<<<CDIV(NATOM*32,BS),BS>>>(cat_a, atom_batch, goff_a, stats,
                                        ln_d_w, ln_d_b, pd_Wrel, pd_Wroot,
                                        atom_h, ta1, ta2, NATOM);

    // layer 2
    k_gemm6<7,1,2,false><<<NATOM/64,224>>>(atom_h, WcA2, hC, nullptr, dotH, 2*NATOM);
    build_csr(m2p_at, m2p_aa, EM2P, NATOM, NAA, deg, part, rowptr_m, csrc_m);

    k_fill_f<<<CDIV(NG*2,BS),BS>>>(stats, NG*2);
    k_gat_node<<<CDIV(NAA*32,BS),BS>>>(rowptr_p, csrc_p, hB,
                                       dotP + 2*NAA, dotP + 4*NAA, bp, aa_batch, stats, cat_p, 0, NAA);
    k_gat_node<<<CDIV(NAA*32,BS),BS>>>(rowptr_m, csrc_m, hC,
                                       dotH, dotP + 6*NAA, bi, aa_batch, stats, cat_p, HCC, NAA);
    k_ln_pool<<<CDIV(NAA*32,BS),BS>>>(cat_p, aa_batch, goff_p, stats,
                                      ln_p_w, ln_p_b, pp_Wrel, pp_Wroot,
                                      out_aa, tp1, tp2, NAA);

    // SAG pool (atoms) + drug_g
    k_sagg_csr<<<CDIV(NATOM,BS),BS>>>(rowptr_a, csrc_a, ta1, sagg, NATOM);
    k_score_g<<<NG,256>>>(sagg, ta2, pd_brel, goff_a, esc, ssum);
    k_fill_f<<<CDIV(NG*DD,BS),BS>>>(out_drug, NG*DD);
    k_final_chunk<<<CDIV(NATOM,64),DD>>>(atom_h, atom_batch, esc, ssum, out_atom, out_drug, NATOM);

    // SAG pool (aa) + prot_g
    k_sagg_csr<<<CDIV(NAA,BS),BS>>>(rowptr_p, csrc_p, tp1, sagg, NAA);
    k_score_g<<<NG,256>>>(sagg, tp2, pp_brel, goff_p, esc, ssum);
    k_fill_f<<<CDIV(NG*DD,BS),BS>>>(out_prot, NG*DD);
    k_final_chunk<<<CDIV(NAA,64),DD>>>(out_aa, aa_batch, esc, ssum, out_aa, out_prot, NAA);
}

// round 16
// speedup vs baseline: 1.3788x; 1.0447x over previous
#include <cuda_runtime.h>
#include <cuda_bf16.h>
#include <math.h>

#define NATOM 25600
#define NAA   204800
#define NG    512
#define DD    200
#define HCC   100
#define EATOM 102400
#define EAA   1024000
#define EM2P  512000
#define KPAD  208

#define OUT_ATOM_OFF 0
#define OUT_AA_OFF   (NATOM*DD)
#define OUT_DRUG_OFF (OUT_AA_OFF + NAA*DD)
#define OUT_PROT_OFF (OUT_DRUG_OFF + NG*DD)

#define CDIV(a,b) (((a)+(b)-1)/(b))

typedef unsigned long long ull;

// ---------------- scratch ----------------
__device__ float g_hA[NAA*HCC];
__device__ float g_hB[NAA*HCC];
__device__ float g_hC[NATOM*HCC];
__device__ float g_cat_atom[NATOM*DD];
__device__ float g_cat_aa[NAA*DD];
__device__ float g_atom_h[NATOM*DD];
__device__ float g_wv[16*DD];
__device__ float g_WcA1[200*112];
__device__ float g_WcA2[200*112];
__device__ __nv_bfloat16 g_Xhi[(long)NAA*KPAD];
__device__ __nv_bfloat16 g_Xlo[(long)NAA*KPAD];
__device__ __nv_bfloat16 g_WhT[KPAD*KPAD];
__device__ __nv_bfloat16 g_WlT[KPAD*KPAD];
__device__ float g_dotA[6*NATOM];
__device__ float g_dotP[8*NAA];
__device__ float g_dotH[2*NATOM];
__device__ float g_stats[NG*2];
__device__ float g_ta1[NATOM];
__device__ float g_ta2[NATOM];
__device__ float g_tp1[NAA];
__device__ float g_tp2[NAA];
__device__ float g_sagg[NAA];
__device__ float g_esc[NAA];
__device__ float g_ssum[NG];
__device__ int g_rowptr_a[NATOM+1];
__device__ int g_csrc_a[EATOM+NATOM];
__device__ int g_rowptr_p[NAA+1];
__device__ int g_csrc_p[EAA+NAA];
__device__ int g_rowptr_m[NAA+1];
__device__ int g_csrc_m[EM2P+NATOM];
__device__ int g_deg[NAA];
__device__ int g_part[512];
__device__ int g_goff_a[NG+1];
__device__ int g_goff_p[NG+1];

// ---------------- utils ----------------
__global__ void k_fill_int(int* p, int n, int v){
    int i = blockIdx.x*blockDim.x + threadIdx.x;
    if (i < n) p[i] = v;
}
__global__ void k_fill_f(float* p, int n){
    int i = blockIdx.x*blockDim.x + threadIdx.x;
    if (i < n) p[i] = 0.f;
}
__device__ __forceinline__ float eluf(float v){ return v > 0.f ? v : expm1f(v); }

// ---------------- scans ----------------
__global__ void k_scan_part(const int* __restrict__ deg, int n, int* __restrict__ part){
    __shared__ int sh[512];
    int t = threadIdx.x;
    int i = blockIdx.x*512 + t;
    sh[t] = (i < n) ? deg[i] : 0;
    __syncthreads();
    for (int off = 256; off > 0; off >>= 1){
        if (t < off) sh[t] += sh[t+off];
        __syncthreads();
    }
    if (!t) part[blockIdx.x] = sh[0];
}
__global__ void k_scan_mid(int* part, int nb){
    __shared__ int sh[512];
    int t = threadIdx.x;
    int x0 = (t < nb) ? part[t] : 0;
    sh[t] = x0;
    __syncthreads();
    for (int off = 1; off < 512; off <<= 1){
        int v = (t >= off) ? sh[t-off] : 0;
        __syncthreads();
        sh[t] += v;
        __syncthreads();
    }
    if (t < nb) part[t] = sh[t] - x0;
}
__global__ void k_scan_final(const int* __restrict__ deg, const int* __restrict__ part,
                             int n, int* __restrict__ rowptr, int* __restrict__ cursor){
    __shared__ int sh[512];
    int t = threadIdx.x;
    int i = blockIdx.x*512 + t;
    int x0 = (i < n) ? deg[i] : 0;
    sh[t] = x0;
    __syncthreads();
    for (int off = 1; off < 512; off <<= 1){
        int v = (t >= off) ? sh[t-off] : 0;
        __syncthreads();
        sh[t] += v;
        __syncthreads();
    }
    if (i < n){
        int inc = sh[t] + part[blockIdx.x];
        rowptr[i+1] = inc;
        cursor[i] = inc - x0;
    }
    if (i == 0) rowptr[0] = 0;
}
__global__ void k_scan512(const int* __restrict__ deg, int* __restrict__ off){
    __shared__ int sh[NG];
    int t = threadIdx.x;
    sh[t] = deg[t];
    __syncthreads();
    for (int o = 1; o < NG; o <<= 1){
        int v = (t >= o) ? sh[t-o] : 0;
        __syncthreads();
        sh[t] += v;
        __syncthreads();
    }
    off[t+1] = sh[t];
    if (!t) off[0] = 0;
}

// ---------------- CSR build ----------------
__global__ void k_deg(const int* __restrict__ dst, int E, int nloop, int* __restrict__ deg){
    int i = blockIdx.x*blockDim.x + threadIdx.x;
    int tot = E + nloop;
    if (i >= tot) return;
    int d = (i < E) ? dst[i] : (i - E);
    atomicAdd(&deg[d], 1);
}
__global__ void k_fill_csr(const int* __restrict__ src, const int* __restrict__ dst,
                           int E, int nloop,
                           int* __restrict__ cursor, int* __restrict__ csrc){
    int i = blockIdx.x*blockDim.x + threadIdx.x;
    int tot = E + nloop;
    if (i >= tot) return;
    int d, v;
    if (i < E){ d = dst[i]; v = src[i]; }
    else      { d = i - E;  v = d | 0x80000000; }
    int pos = atomicAdd(&cursor[d], 1);
    csrc[pos] = v;
}

// ---------------- w-tilde ----------------
__global__ void k_wtilde(const float* __restrict__ Wd, const float* __restrict__ ad_src,
                         const float* __restrict__ ad_dst,
                         const float* __restrict__ Wp, const float* __restrict__ ap_src,
                         const float* __restrict__ ap_dst,
                         const float* __restrict__ Wi_src, const float* __restrict__ ai_src,
                         const float* __restrict__ Wi_dst, const float* __restrict__ ai_dst,
                         float* __restrict__ wv){
    int d = threadIdx.x;
    if (d >= DD) return;
    const float* Ws[16]  = {Wd,Wd,Wd,Wd, Wi_dst,Wi_dst, Wi_src,Wi_src, Wp,Wp, Wp,Wp, Wi_dst,Wi_dst, Wi_src,Wi_src};
    const float* as[16]  = {ad_src,ad_src,ad_dst,ad_dst, ai_dst,ai_dst, ai_src,ai_src,
                            ap_src,ap_src, ap_dst,ap_dst, ai_dst,ai_dst, ai_src,ai_src};
    const int    hs[16]  = {0,1,0,1, 0,1, 0,1, 0,1, 0,1, 0,1, 0,1};
    for (int slot = 0; slot < 16; slot++){
        const float* W = Ws[slot]; const float* a = as[slot]; int h = hs[slot];
        float s = 0.f;
        for (int c = 0; c < 50; c++) s += W[d*HCC + h*50 + c]*a[h*50 + c];
        wv[slot*DD + d] = s;
    }
}

// ---------------- combined weights + transposed bf16 split W ----------------
__global__ void k_prepW2(const float* __restrict__ Wd, const float* __restrict__ Wp,
                         const float* __restrict__ Wi_src, const float* __restrict__ wv,
                         float* __restrict__ WcA1, float* __restrict__ WcA2,
                         __nv_bfloat16* __restrict__ WhT, __nv_bfloat16* __restrict__ WlT){
    int i = blockIdx.x*blockDim.x + threadIdx.x;
    const int S1 = 200*112;
    if (i < S1){
        int k = i/112, c = i%112;
        float v = 0.f;
        if (c < 100) v = Wd[k*HCC + c];
        else if (c < 106) v = wv[(c-100)*DD + k];
        WcA1[i] = v;
    } else if (i < 2*S1){
        int j = i - S1; int k = j/112, c = j%112;
        float v = 0.f;
        if (c < 100) v = Wi_src[k*HCC + c];
        else if (c < 102) v = wv[(14 + (c-100))*DD + k];
        WcA2[j] = v;
    } else if (i < 2*S1 + KPAD*KPAD){
        int j = i - 2*S1; int n = j / KPAD, k = j % KPAD;
        float v = 0.f;
        if (k < 200){
            if (n < 100) v = Wi_src[k*HCC + n];
            else if (n < 200) v = Wp[k*HCC + (n-100)];
            else v = wv[(6 + (n-200))*DD + k];
        }
        __nv_bfloat16 h = __float2bfloat16(v);
        float hv = __bfloat162float(h);
        WhT[j] = h;
        WlT[j] = __float2bfloat16(v - hv);
    }
}

// ---------------- X conversion: elu + bf16 split, K padded to 208 ----------------
__global__ void k_cvt_x(const float* __restrict__ x,
                        __nv_bfloat16* __restrict__ hi, __nv_bfloat16* __restrict__ lo){
    long i = (long)blockIdx.x*blockDim.x + threadIdx.x;
    long tot = (long)NAA*KPAD;
    if (i >= tot) return;
    int col = (int)(i % KPAD);
    long row = i / KPAD;
    float v = 0.f;
    if (col < 200) v = eluf(x[row*DD + col]);
    __nv_bfloat16 h = __float2bfloat16(v);
    float hv = __bfloat162float(h);
    hi[i] = h;
    lo[i] = __float2bfloat16(v - hv);
}

// ---------------- HMMA dual GEMM v4: W smem-resident, barrier-free mainloop ----------------
#define WPITCH 216
#define SM_BYTES (2*KPAD*WPITCH*2)

#define MMA16816(d, a, b0, b1) \
    asm volatile("mma.sync.aligned.m16n8k16.row.col.f32.bf16.bf16.f32 " \
        "{%0,%1,%2,%3}, {%4,%5,%6,%7}, {%8,%9}, {%0,%1,%2,%3};" \
        : "+f"((d)[0]),"+f"((d)[1]),"+f"((d)[2]),"+f"((d)[3]) \
        : "r"((a)[0]),"r"((a)[1]),"r"((a)[2]),"r"((a)[3]), "r"(b0),"r"(b1))

__global__ __launch_bounds__(512,1)
void k_hmma(const __nv_bfloat16* __restrict__ Xhi, const __nv_bfloat16* __restrict__ Xlo,
            const __nv_bfloat16* __restrict__ Bhg, const __nv_bfloat16* __restrict__ Blg,
            float* __restrict__ O0, float* __restrict__ O1,
            float* __restrict__ dots, int twoN){
    extern __shared__ __nv_bfloat16 sm[];
    __nv_bfloat16* Wh = sm;
    __nv_bfloat16* Wl = sm + KPAD*WPITCH;
    int tid = threadIdx.x;
    int wid = tid >> 5, lane = tid & 31;
    int wm = wid & 7, wn = wid >> 3;
    int g = lane >> 2, tig = lane & 3;
    long row0 = (long)blockIdx.x * 128;

    for (int u = tid; u < KPAD*104; u += 512){
        int n = u / 104, kp = u % 104;
        *(unsigned*)&Wh[n*WPITCH + kp*2] = *(const unsigned*)(Bhg + (long)n*KPAD + kp*2);
        *(unsigned*)&Wl[n*WPITCH + kp*2] = *(const unsigned*)(Blg + (long)n*KPAD + kp*2);
    }
    __syncthreads();

    float acc[13][4];
    #pragma unroll
    for (int j = 0; j < 13; j++)
        #pragma unroll
        for (int q = 0; q < 4; q++) acc[j][q] = 0.f;

    long ar0 = (row0 + wm*16 + g)*KPAD + tig*2;
    long ar8 = ar0 + 8*KPAD;

    unsigned ah[4], al[4], pah[4], pal[4];
    pah[0] = *(const unsigned*)(Xhi + ar0);
    pah[1] = *(const unsigned*)(Xhi + ar8);
    pah[2] = *(const unsigned*)(Xhi + ar0 + 8);
    pah[3] = *(const unsigned*)(Xhi + ar8 + 8);
    pal[0] = *(const unsigned*)(Xlo + ar0);
    pal[1] = *(const unsigned*)(Xlo + ar8);
    pal[2] = *(const unsigned*)(Xlo + ar0 + 8);
    pal[3] = *(const unsigned*)(Xlo + ar8 + 8);

    for (int kc = 0; kc < 13; kc++){
        #pragma unroll
        for (int q = 0; q < 4; q++){ ah[q] = pah[q]; al[q] = pal[q]; }
        if (kc < 12){
            int k0 = (kc+1)*16;
            pah[0] = *(const unsigned*)(Xhi + ar0 + k0);
            pah[1] = *(const unsigned*)(Xhi + ar8 + k0);
            pah[2] = *(const unsigned*)(Xhi + ar0 + k0 + 8);
            pah[3] = *(const unsigned*)(Xhi + ar8 + k0 + 8);
            pal[0] = *(const unsigned*)(Xlo + ar0 + k0);
            pal[1] = *(const unsigned*)(Xlo + ar8 + k0);
            pal[2] = *(const unsigned*)(Xlo + ar0 + k0 + 8);
            pal[3] = *(const unsigned*)(Xlo + ar8 + k0 + 8);
        }
        int kb = kc*16 + tig*2;
        #pragma unroll
        for (int j = 0; j < 13; j++){
            int nrow = wn*104 + j*8 + g;
            const __nv_bfloat16* wph = &Wh[nrow*WPITCH + kb];
            const __nv_bfloat16* wpl = &Wl[nrow*WPITCH + kb];
            unsigned bh0 = *(const unsigned*)wph;
            unsigned bh1 = *(const unsigned*)(wph + 8);
            unsigned bl0 = *(const unsigned*)wpl;
            unsigned bl1 = *(const unsigned*)(wpl + 8);
            MMA16816(acc[j], ah, bh0, bh1);
            MMA16816(acc[j], ah, bl0, bl1);
            MMA16816(acc[j], al, bh0, bh1);
        }
    }

    long r_hi = row0 + wm*16 + g;
    long r_lo = r_hi + 8;
    #pragma unroll
    for (int j = 0; j < 13; j++){
        int colb = wn*104 + j*8 + tig*2;
        #pragma unroll
        for (int h = 0; h < 2; h++){
            long row = h ? r_lo : r_hi;
            float2 v = make_float2(acc[j][2*h], acc[j][2*h+1]);
            if (colb < 100)      *(float2*)&O0[row*HCC + colb] = v;
            else if (colb < 200) *(float2*)&O1[row*HCC + (colb-100)] = v;
            else {
                int pr = (colb - 200) >> 1;
                *(float2*)&dots[(long)pr*twoN + row*2] = v;
            }
        }
    }
}

// ---------------- GEMM v6 (fp32 FMA2, atom-side) ----------------
#define FMA2(acc, x, w) asm("fma.rn.f32x2 %0, %1, %2, %0;" : "+l"(acc) : "l"(x), "l"(w))
#define DUP2(dst, f)    asm("mov.b64 %0, {%1, %1};" : "=l"(dst) : "r"(__float_as_uint(f)))

template<int NW, int NOUT, int NDOT, bool ELU>
__global__ __launch_bounds__(NW*32, 2)
void k_gemm6(const float* __restrict__ X, const float* __restrict__ Wc,
             float* __restrict__ O0, float* __restrict__ O1,
             float* __restrict__ dots, int twoN){
    constexpr int NC = NW*16;
    constexpr int T  = NW*32;
    constexpr int NXF = (320 + T - 1)/T;
    constexpr int NWF = (20*NC + T - 1)/T;
    __shared__ __align__(16) float Xs[20][64];
    __shared__ __align__(16) float Ws[20*NC];
    int tid = threadIdx.x;
    int wi = tid >> 5, lane = tid & 31;
    long row0 = (long)blockIdx.x * 64;

    float4 xv[NXF];
    float wreg[NWF];

    #pragma unroll
    for (int i = 0; i < NXF; i++){
        int u = tid + i*T;
        if (u < 320){
            int r = u/5, q = u%5;
            float4 v = *(const float4*)&X[(row0+r)*DD + q*4];
            if (ELU){ v.x=eluf(v.x); v.y=eluf(v.y); v.z=eluf(v.z); v.w=eluf(v.w); }
            xv[i] = v;
        }
    }
    #pragma unroll
    for (int i = 0; i < NWF; i++){
        int u = tid + i*T;
        if (u < 20*NC) wreg[i] = Wc[u];
    }

    ull acc[2][8];
    #pragma unroll
    for (int r = 0; r < 2; r++)
        #pragma unroll
        for (int j = 0; j < 8; j++) acc[r][j] = 0ull;

    for (int it = 0; it < 10; it++){
        if (it) __syncthreads();
        #pragma unroll
        for (int i = 0; i < NXF; i++){
            int u = tid + i*T;
            if (u < 320){
                int r = u/5, q = u%5;
                #pragma unroll
                for (int j = 0; j < 4; j++)
                    Xs[q*4+j][r] = ((const float*)&xv[i])[j];
            }
        }
        #pragma unroll
        for (int i = 0; i < NWF; i++){
            int u = tid + i*T;
            if (u < 20*NC) Ws[u] = wreg[i];
        }
        __syncthreads();
        if (it < 9){
            int k0n = (it+1)*20;
            #pragma unroll
            for (int i = 0; i < NXF; i++){
                int u = tid + i*T;
                if (u < 320){
                    int r = u/5, q = u%5;
                    float4 v = *(const float4*)&X[(row0+r)*DD + k0n + q*4];
                    if (ELU){ v.x=eluf(v.x); v.y=eluf(v.y); v.z=eluf(v.z); v.w=eluf(v.w); }
                    xv[i] = v;
                }
            }
            #pragma unroll
            for (int i = 0; i < NWF; i++){
                int u = tid + i*T;
                if (u < 20*NC) wreg[i] = Wc[k0n*NC + u];
            }
        }
        #pragma unroll 5
        for (int k = 0; k < 20; k++){
            float2 x2 = *(const float2*)&Xs[k][2*lane];
            ull xlo, xhi;
            DUP2(xlo, x2.x);
            DUP2(xhi, x2.y);
            const ulonglong2* wp = (const ulonglong2*)&Ws[k*NC + wi*16];
            ulonglong2 wA = wp[0], wB = wp[1], wC = wp[2], wD = wp[3];
            ull wc8[8] = {wA.x, wA.y, wB.x, wB.y, wC.x, wC.y, wD.x, wD.y};
            #pragma unroll
            for (int j = 0; j < 8; j++){
                FMA2(acc[0][j], xlo, wc8[j]);
                FMA2(acc[1][j], xhi, wc8[j]);
            }
        }
    }

    #pragma unroll
    for (int j = 0; j < 8; j++){
        int col = wi*16 + 2*j;
        long r0 = row0 + 2*lane;
        if (col < 100){
            *(ull*)&O0[r0*HCC + col]     = acc[0][j];
            *(ull*)&O0[(r0+1)*HCC + col] = acc[1][j];
        } else if (NOUT == 2 && col < 200){
            *(ull*)&O1[r0*HCC + (col-100)]     = acc[0][j];
            *(ull*)&O1[(r0+1)*HCC + (col-100)] = acc[1][j];
        } else if (col >= 100*NOUT && col < 100*NOUT + NDOT){
            int pr = (col - 100*NOUT) >> 1;
            *(ull*)&dots[(long)pr*twoN + r0*2]     = acc[0][j];
            *(ull*)&dots[(long)pr*twoN + (r0+1)*2] = acc[1][j];
        }
    }
}

// ---------------- fused GAT aggregation + LN stats (unrolled x2, __expf) ----------------
__global__ void k_gat_node(const int* __restrict__ rowptr, const int* __restrict__ csrc,
                           const float* __restrict__ hs,
                           const float* __restrict__ als, const float* __restrict__ ald,
                           const float* __restrict__ bias, const int* __restrict__ batch,
                           float* __restrict__ stats,
                           float* __restrict__ out, int coloff, int n){
    int w = (blockIdx.x*blockDim.x + threadIdx.x) >> 5;
    int lane = threadIdx.x & 31;
    if (w >= n) return;
    float2 aldv = *(const float2*)&ald[2*w];
    int beg = rowptr[w], end = rowptr[w+1];
    float a0 = 0.f, a1 = 0.f, a2 = 0.f, a3 = 0.f, z0 = 0.f, z1 = 0.f;
    int j = beg;
    for (; j + 2 <= end; j += 2){
        int s0 = csrc[j]   & 0x7fffffff;
        int s1 = csrc[j+1] & 0x7fffffff;
        float2 A0 = *(const float2*)&als[2*s0];
        float2 A1 = *(const float2*)&als[2*s1];
        const float* h0 = hs + (long)s0*HCC;
        const float* h1 = hs + (long)s1*HCC;
        float u00 = h0[lane], u01 = h0[lane+32], u02 = h0[lane+64];
        float u10 = h1[lane], u11 = h1[lane+32], u12 = h1[lane+64];
        float u03 = (lane < 4) ? h0[lane+96] : 0.f;
        float u13 = (lane < 4) ? h1[lane+96] : 0.f;
        float l00 = A0.x + aldv.x, l01 = A0.y + aldv.y;
        float l10 = A1.x + aldv.x, l11 = A1.y + aldv.y;
        l00 = l00 > 0.f ? l00 : 0.2f*l00;
        l01 = l01 > 0.f ? l01 : 0.2f*l01;
        l10 = l10 > 0.f ? l10 : 0.2f*l10;
        l11 = l11 > 0.f ? l11 : 0.2f*l11;
        float e00 = __expf(l00), e01 = __expf(l01);
        float e10 = __expf(l10), e11 = __expf(l11);
        z0 += e00 + e10; z1 += e01 + e11;
        a0 += e00*u00 + e10*u10;
        float w0m = (lane < 18) ? e00 : e01;
        float w1m = (lane < 18) ? e10 : e11;
        a1 += w0m*u01 + w1m*u11;
        a2 += e01*u02 + e11*u12;
        a3 += e01*u03 + e11*u13;
    }
    if (j < end){
        int s = csrc[j] & 0x7fffffff;
        float2 A = *(const float2*)&als[2*s];
        const float* h = hs + (long)s*HCC;
        float l0 = A.x + aldv.x, l1 = A.y + aldv.y;
        l0 = l0 > 0.f ? l0 : 0.2f*l0;
        l1 = l1 > 0.f ? l1 : 0.2f*l1;
        float e0 = __expf(l0), e1 = __expf(l1);
        z0 += e0; z1 += e1;
        a0 += e0*h[lane];
        a1 += ((lane < 18) ? e0 : e1)*h[lane+32];
        a2 += e1*h[lane+64];
        if (lane < 4) a3 += e1*h[lane+96];
    }
    float iz0 = 1.f/(z0 + 1e-16f), iz1 = 1.f/(z1 + 1e-16f);
    float o0 = bias[lane]    + a0*iz0;
    float o1 = bias[lane+32] + a1*(lane < 18 ? iz0 : iz1);
    float o2 = bias[lane+64] + a2*iz1;
    float o3 = (lane < 4) ? (bias[lane+96] + a3*iz1) : 0.f;
    float* o = out + (long)w*DD + coloff;
    o[lane]    = o0;
    o[lane+32] = o1;
    o[lane+64] = o2;
    if (lane < 4) o[lane+96] = o3;
    float s  = o0 + o1 + o2 + o3;
    float s2 = o0*o0 + o1*o1 + o2*o2 + o3*o3;
    #pragma unroll
    for (int off = 16; off > 0; off >>= 1){
        s  += __shfl_down_sync(0xffffffffu, s,  off);
        s2 += __shfl_down_sync(0xffffffffu, s2, off);
    }
    if (!lane){
        int b = batch[w];
        atomicAdd(&stats[2*b],   s);
        atomicAdd(&stats[2*b+1], s2);
    }
}

// ---------------- warp-per-row LN apply + ELU + fused SAG dots ----------------
__global__ void k_ln_pool(const float* __restrict__ x, const int* __restrict__ batch,
                          const int* __restrict__ goff, const float* __restrict__ stats,
                          const float* __restrict__ w, const float* __restrict__ bia,
                          const float* __restrict__ wrel, const float* __restrict__ wroot,
                          float* __restrict__ y, float* __restrict__ t1,
                          float* __restrict__ t2, int n){
    __shared__ float sw[DD], sb[DD], sr[DD], so[DD];
    for (int i = threadIdx.x; i < DD; i += blockDim.x){
        sw[i] = w[i]; sb[i] = bia[i]; sr[i] = wrel[i]; so[i] = wroot[i];
    }
    __syncthreads();
    int row = (blockIdx.x*blockDim.x + threadIdx.x) >> 5;
    int lane = threadIdx.x & 31;
    if (row >= n) return;
    int b = batch[row];
    float cnt = (float)(goff[b+1] - goff[b]);
    float norm = fmaxf(cnt, 1.f) * (float)DD;
    float mean = stats[2*b] / norm;
    float var  = stats[2*b+1] / norm - mean*mean;
    float rs   = rsqrtf(fmaxf(var, 0.f) + 1e-5f);
    const float* xr = x + (long)row*DD;
    float* yr = y + (long)row*DD;
    float a = 0.f, bb = 0.f;
    #pragma unroll
    for (int c = lane; c < DD; c += 32){
        float v = eluf((xr[c] - mean)*rs*sw[c] + sb[c]);
        yr[c] = v;
        a  += v*sr[c];
        bb += v*so[c];
    }
    #pragma unroll
    for (int off = 16; off > 0; off >>= 1){
        a  += __shfl_down_sync(0xffffffffu, a,  off);
        bb += __shfl_down_sync(0xffffffffu, bb, off);
    }
    if (!lane){ t1[row] = a; t2[row] = bb; }
}

// ---------------- SAG pooling ----------------
__global__ void k_sagg_csr(const int* __restrict__ rowptr, const int* __restrict__ csrc,
                           const float* __restrict__ t1, float* __restrict__ sagg, int n){
    int i = blockIdx.x*blockDim.x + threadIdx.x;
    if (i >= n) return;
    float s = 0.f;
    int beg = rowptr[i], end = rowptr[i+1];
    for (int j = beg; j < end; j++){
        int v = csrc[j];
        if (v >= 0) s += t1[v];
    }
    sagg[i] = s;
}
__global__ void k_score_g(const float* __restrict__ sagg, const float* __restrict__ t2,
                          const float* __restrict__ brel, const int* __restrict__ goff,
                          float* __restrict__ e, float* __restrict__ ssum){
    int g = blockIdx.x;
    int beg = goff[g], end = goff[g+1];
    int t = threadIdx.x;
    float b0 = brel[0];
    __shared__ float red[256];
    float m = -3.4e38f;
    for (int r = beg + t; r < end; r += 256)
        m = fmaxf(m, sagg[r] + b0 + t2[r]);
    red[t] = m;
    __syncthreads();
    for (int off = 128; off > 0; off >>= 1){
        if (t < off) red[t] = fmaxf(red[t], red[t+off]);
        __syncthreads();
    }
    m = red[0];
    __syncthreads();
    float s = 0.f;
    for (int r = beg + t; r < end; r += 256){
        float v = __expf(sagg[r] + b0 + t2[r] - m);
        e[r] = v; s += v;
    }
    red[t] = s;
    __syncthreads();
    for (int off = 128; off > 0; off >>= 1){
        if (t < off) red[t] += red[t+off];
        __syncthreads();
    }
    if (!t) ssum[g] = red[0];
}
__global__ void k_final_chunk(const float* __restrict__ x, const int* __restrict__ batch,
                              const float* __restrict__ e, const float* __restrict__ ssum,
                              float* __restrict__ out, float* __restrict__ gsum, int n){
    int c = threadIdx.x;
    int r0 = blockIdx.x*64;
    int r1 = min(r0 + 64, n);
    int gcur = batch[r0];
    float inv = 1.f/(ssum[gcur] + 1e-16f);
    float acc = 0.f;
    for (int r = r0; r < r1; r++){
        int g = batch[r];
        if (g != gcur){
            atomicAdd(&gsum[gcur*DD + c], acc);
            acc = 0.f; gcur = g;
            inv = 1.f/(ssum[g] + 1e-16f);
        }
        float sc = e[r]*inv;
        float v = x[(long)r*DD + c]*sc;
        out[(long)r*DD + c] = v;
        acc += v;
    }
    atomicAdd(&gsum[gcur*DD + c], acc);
}

// ---------------- host ----------------
static void* symaddr(const void* s){ void* p = nullptr; cudaGetSymbolAddress(&p, s); return p; }

static void build_csr(const int* src, const int* dst, int E, int nloop, int n,
                      int* deg, int* part, int* rowptr, int* csrc){
    int nb = CDIV(n, 512);
    k_fill_int<<<CDIV(n,256),256>>>(deg, n, 0);
    k_deg<<<CDIV(E+nloop,256),256>>>(dst, E, nloop, deg);
    k_scan_part<<<nb,512>>>(deg, n, part);
    k_scan_mid<<<1,512>>>(part, nb);
    k_scan_final<<<nb,512>>>(deg, part, n, rowptr, deg);
    k_fill_csr<<<CDIV(E+nloop,256),256>>>(src, dst, E, nloop, deg, csrc);
}

extern "C" void kernel_launch(void* const* d_in, const int* in_sizes, int n_in,
                              void* d_out, int out_size){
    const float* atom_x    = (const float*)d_in[0];
    const int*   atom_ei   = (const int*)  d_in[1];
    const int*   atom_batch= (const int*)  d_in[2];
    const float* aa_x      = (const float*)d_in[3];
    const int*   aa_ei     = (const int*)  d_in[4];
    const int*   aa_batch  = (const int*)  d_in[6];
    const int*   m2p       = (const int*)  d_in[7];
    const float* Wd     = (const float*)d_in[8];
    const float* ad_src = (const float*)d_in[9];
    const float* ad_dst = (const float*)d_in[10];
    const float* bd     = (const float*)d_in[11];
    const float* Wp     = (const float*)d_in[12];
    const float* ap_src = (const float*)d_in[13];
    const float* ap_dst = (const float*)d_in[14];
    const float* bp     = (const float*)d_in[15];
    const float* Wi_src = (const float*)d_in[16];
    const float* Wi_dst = (const float*)d_in[17];
    const float* ai_src = (const float*)d_in[18];
    const float* ai_dst = (const float*)d_in[19];
    const float* bi     = (const float*)d_in[20];
    const float* ln_d_w = (const float*)d_in[21];
    const float* ln_d_b = (const float*)d_in[22];
    const float* ln_p_w = (const float*)d_in[23];
    const float* ln_p_b = (const float*)d_in[24];
    const float* pd_Wrel  = (const float*)d_in[25];
    const float* pd_brel  = (const float*)d_in[26];
    const float* pd_Wroot = (const float*)d_in[27];
    const float* pp_Wrel  = (const float*)d_in[28];
    const float* pp_brel  = (const float*)d_in[29];
    const float* pp_Wroot = (const float*)d_in[30];

    float* hA     = (float*)symaddr(g_hA);
    float* hB     = (float*)symaddr(g_hB);
    float* hC     = (float*)symaddr(g_hC);
    float* cat_a  = (float*)symaddr(g_cat_atom);
    float* cat_p  = (float*)symaddr(g_cat_aa);
    float* atom_h = (float*)symaddr(g_atom_h);
    float* wv     = (float*)symaddr(g_wv);
    float* WcA1   = (float*)symaddr(g_WcA1);
    float* WcA2   = (float*)symaddr(g_WcA2);
    __nv_bfloat16* Xhi = (__nv_bfloat16*)symaddr(g_Xhi);
    __nv_bfloat16* Xlo = (__nv_bfloat16*)symaddr(g_Xlo);
    __nv_bfloat16* WhT = (__nv_bfloat16*)symaddr(g_WhT);
    __nv_bfloat16* WlT = (__nv_bfloat16*)symaddr(g_WlT);
    float* dotA   = (float*)symaddr(g_dotA);
    float* dotP   = (float*)symaddr(g_dotP);
    float* dotH   = (float*)symaddr(g_dotH);
    float* stats  = (float*)symaddr(g_stats);
    float* ta1    = (float*)symaddr(g_ta1);
    float* ta2    = (float*)symaddr(g_ta2);
    float* tp1    = (float*)symaddr(g_tp1);
    float* tp2    = (float*)symaddr(g_tp2);
    float* sagg   = (float*)symaddr(g_sagg);
    float* esc    = (float*)symaddr(g_esc);
    float* ssum   = (float*)symaddr(g_ssum);
    int* rowptr_a = (int*)symaddr(g_rowptr_a);
    int* csrc_a   = (int*)symaddr(g_csrc_a);
    int* rowptr_p = (int*)symaddr(g_rowptr_p);
    int* csrc_p   = (int*)symaddr(g_csrc_p);
    int* rowptr_m = (int*)symaddr(g_rowptr_m);
    int* csrc_m   = (int*)symaddr(g_csrc_m);
    int* deg      = (int*)symaddr(g_deg);
    int* part     = (int*)symaddr(g_part);
    int* goff_a   = (int*)symaddr(g_goff_a);
    int* goff_p   = (int*)symaddr(g_goff_p);

    float* out      = (float*)d_out;
    float* out_atom = out + OUT_ATOM_OFF;
    float* out_aa   = out + OUT_AA_OFF;
    float* out_drug = out + OUT_DRUG_OFF;
    float* out_prot = out + OUT_PROT_OFF;

    const int BS = 256;
    const int* atom_src = atom_ei;  const int* atom_dst = atom_ei + EATOM;
    const int* aa_src   = aa_ei;    const int* aa_dst   = aa_ei + EAA;
    const int* m2p_at   = m2p;      const int* m2p_aa   = m2p + EM2P;

    cudaFuncSetAttribute(k_hmma, cudaFuncAttributeMaxDynamicSharedMemorySize, SM_BYTES);

    // 0: w-tilde, 1: weights, 2: X conversion
    k_wtilde<<<1,224>>>(Wd, ad_src, ad_dst, Wp, ap_src, ap_dst,
                        Wi_src, ai_src, Wi_dst, ai_dst, wv);
    k_prepW2<<<CDIV(2*200*112 + KPAD*KPAD, BS),BS>>>(Wd, Wp, Wi_src, wv, WcA1, WcA2, WhT, WlT);
    k_cvt_x<<<CDIV((long)NAA*KPAD, BS),BS>>>(aa_x, Xhi, Xlo);
    // 3: HMMA dual GEMM
    k_hmma<<<NAA/128, 512, SM_BYTES>>>(Xhi, Xlo, WhT, WlT, hA, hB, dotP, 2*NAA);
    // 4: atom layer-1 GEMM (+6 dot cols)
    k_gemm6<7,1,6,true><<<NATOM/64,224>>>(atom_x, WcA1, hC, nullptr, dotA, 2*NATOM);

    // graph offsets
    k_fill_int<<<CDIV(NG,BS),BS>>>(deg, NG, 0);
    k_deg<<<CDIV(NATOM,BS),BS>>>(atom_batch, NATOM, 0, deg);
    k_scan512<<<1,NG>>>(deg, goff_a);
    k_fill_int<<<CDIV(NG,BS),BS>>>(deg, NG, 0);
    k_deg<<<CDIV(NAA,BS),BS>>>(aa_batch, NAA, 0, deg);
    k_scan512<<<1,NG>>>(deg, goff_p);

    // CSR builds
    build_csr(atom_src, atom_dst, EATOM, NATOM, NATOM, deg, part, rowptr_a, csrc_a);
    build_csr(aa_src,   aa_dst,   EAA,   NAA,   NAA,   deg, part, rowptr_p, csrc_p);
    build_csr(m2p_aa,   m2p_at,   EM2P,  NATOM, NATOM, deg, part, rowptr_m, csrc_m);

    // GAT1 + GAT2 + fused LN stats -> cat_a
    k_fill_f<<<CDIV(NG*2,BS),BS>>>(stats, NG*2);
    k_gat_node<<<CDIV(NATOM*32,BS),BS>>>(rowptr_a, csrc_a, hC,
                                         dotA, dotA + 2*NATOM, bd, atom_batch, stats, cat_a, 0, NATOM);
    k_gat_node<<<CDIV(NATOM*32,BS),BS>>>(rowptr_m, csrc_m, hA,
                                         dotP, dotA + 4*NATOM, bi, atom_batch, stats, cat_a, HCC, NATOM);
    k_ln_pool<<<CDIV(NATOM*32,BS),BS>>>(cat_a, atom_batch, goff_a, stats,
                                        ln_d_w, ln_d_b, pd_Wrel, pd_Wroot,
                                        atom_h, ta1, ta2, NATOM);

    // layer 2
    k_gemm6<7,1,2,false><<<NATOM/64,224>>>(atom_h, WcA2, hC, nullptr, dotH, 2*NATOM);
    build_csr(m2p_at, m2p_aa, EM2P, NATOM, NAA, deg, part, rowptr_m, csrc_m);

    k_fill_f<<<CDIV(NG*2,BS),BS>>>(stats, NG*2);
    k_gat_node<<<CDIV(NAA*32,BS),BS>>>(rowptr_p, csrc_p, hB,
                                       dotP + 2*NAA, dotP + 4*NAA, bp, aa_batch, stats, cat_p, 0, NAA);
    k_gat_node<<<CDIV(NAA*32,BS),BS>>>(rowptr_m, csrc_m, hC,
                                       dotH, dotP + 6*NAA, bi, aa_batch, stats, cat_p, HCC, NAA);
    k_ln_pool<<<CDIV(NAA*32,BS),BS>>>(cat_p, aa_batch, goff_p, stats,
                                      ln_p_w, ln_p_b, pp_Wrel, pp_Wroot,
                                      out_aa, tp1, tp2, NAA);

    // SAG pool (atoms) + drug_g
    k_sagg_csr<<<CDIV(NATOM,BS),BS>>>(rowptr_a, csrc_a, ta1, sagg, NATOM);
    k_score_g<<<NG,256>>>(sagg, ta2, pd_brel, goff_a, esc, ssum);
    k_fill_f<<<CDIV(NG*DD,BS),BS>>>(out_drug, NG*DD);
    k_final_chunk<<<CDIV(NATOM,64),DD>>>(atom_h, atom_batch, esc, ssum, out_atom, out_drug, NATOM);

    // SAG pool (aa) + prot_g
    k_sagg_csr<<<CDIV(NAA,BS),BS>>>(rowptr_p, csrc_p, tp1, sagg, NAA);
    k_score_g<<<NG,256>>>(sagg, tp2, pp_brel, goff_p, esc, ssum);
    k_fill_f<<<CDIV(NG*DD,BS),BS>>>(out_prot, NG*DD);
    k_final_chunk<<<CDIV(NAA,64),DD>>>(out_aa, aa_batch, esc, ssum, out_aa, out_prot, NAA);
}

// round 17
// speedup vs baseline: 1.4054x; 1.0193x over previous
#include <cuda_runtime.h>
#include <cuda_bf16.h>
#include <math.h>

#define NATOM 25600
#define NAA   204800
#define NG    512
#define DD    200
#define HCC   100
#define EATOM 102400
#define EAA   1024000
#define EM2P  512000
#define KPAD  208

#define OUT_ATOM_OFF 0
#define OUT_AA_OFF   (NATOM*DD)
#define OUT_DRUG_OFF (OUT_AA_OFF + NAA*DD)
#define OUT_PROT_OFF (OUT_DRUG_OFF + NG*DD)

#define CDIV(a,b) (((a)+(b)-1)/(b))

typedef unsigned long long ull;

// ---------------- scratch ----------------
__device__ float g_hA[NAA*HCC];
__device__ float g_hB[NAA*HCC];
__device__ float g_hC[NATOM*HCC];
__device__ float g_cat_atom[NATOM*DD];
__device__ float g_cat_aa[NAA*DD];
__device__ float g_atom_h[NATOM*DD];
__device__ float g_wv[16*DD];
__device__ float g_WcA1[200*112];
__device__ float g_WcA2[200*112];
__device__ __nv_bfloat16 g_Xhi[(long)NAA*KPAD];
__device__ __nv_bfloat16 g_Xlo[(long)NAA*KPAD];
__device__ __nv_bfloat16 g_WhT[KPAD*KPAD];
__device__ __nv_bfloat16 g_WlT[KPAD*KPAD];
__device__ float g_dotA[6*NATOM];
__device__ float g_dotP[8*NAA];
__device__ float g_dotH[2*NATOM];
__device__ float g_stats[NG*2];
__device__ float g_ta1[NATOM];
__device__ float g_ta2[NATOM];
__device__ float g_tp1[NAA];
__device__ float g_tp2[NAA];
__device__ float g_sagg[NAA];
__device__ float g_esc[NAA];
__device__ float g_ssum[NG];
__device__ int g_rowptr_a[NATOM+1];
__device__ int g_csrc_a[EATOM+NATOM];
__device__ int g_rowptr_p[NAA+1];
__device__ int g_csrc_p[EAA+NAA];
__device__ int g_rowptr_m[NATOM+1];
__device__ int g_csrc_m[EM2P+NATOM];
__device__ int g_rowptr_m2[NAA+1];
__device__ int g_csrc_m2[EM2P+NATOM];
__device__ int g_deg[NAA];
__device__ int g_part[512];
__device__ int g_goff_a[NG+1];
__device__ int g_goff_p[NG+1];

// ---------------- utils ----------------
__global__ void k_fill_int(int* p, int n, int v){
    int i = blockIdx.x*blockDim.x + threadIdx.x;
    if (i < n) p[i] = v;
}
__global__ void k_fill_f(float* p, int n){
    int i = blockIdx.x*blockDim.x + threadIdx.x;
    if (i < n) p[i] = 0.f;
}
__device__ __forceinline__ float eluf(float v){ return v > 0.f ? v : expm1f(v); }

// ---------------- scans ----------------
__global__ void k_scan_part(const int* __restrict__ deg, int n, int* __restrict__ part){
    __shared__ int sh[512];
    int t = threadIdx.x;
    int i = blockIdx.x*512 + t;
    sh[t] = (i < n) ? deg[i] : 0;
    __syncthreads();
    for (int off = 256; off > 0; off >>= 1){
        if (t < off) sh[t] += sh[t+off];
        __syncthreads();
    }
    if (!t) part[blockIdx.x] = sh[0];
}
__global__ void k_scan_mid(int* part, int nb){
    __shared__ int sh[512];
    int t = threadIdx.x;
    int x0 = (t < nb) ? part[t] : 0;
    sh[t] = x0;
    __syncthreads();
    for (int off = 1; off < 512; off <<= 1){
        int v = (t >= off) ? sh[t-off] : 0;
        __syncthreads();
        sh[t] += v;
        __syncthreads();
    }
    if (t < nb) part[t] = sh[t] - x0;
}
__global__ void k_scan_final(const int* __restrict__ deg, const int* __restrict__ part,
                             int n, int* __restrict__ rowptr, int* __restrict__ cursor){
    __shared__ int sh[512];
    int t = threadIdx.x;
    int i = blockIdx.x*512 + t;
    int x0 = (i < n) ? deg[i] : 0;
    sh[t] = x0;
    __syncthreads();
    for (int off = 1; off < 512; off <<= 1){
        int v = (t >= off) ? sh[t-off] : 0;
        __syncthreads();
        sh[t] += v;
        __syncthreads();
    }
    if (i < n){
        int inc = sh[t] + part[blockIdx.x];
        rowptr[i+1] = inc;
        cursor[i] = inc - x0;
    }
    if (i == 0) rowptr[0] = 0;
}
__global__ void k_scan512(const int* __restrict__ deg, int* __restrict__ off){
    __shared__ int sh[NG];
    int t = threadIdx.x;
    sh[t] = deg[t];
    __syncthreads();
    for (int o = 1; o < NG; o <<= 1){
        int v = (t >= o) ? sh[t-o] : 0;
        __syncthreads();
        sh[t] += v;
        __syncthreads();
    }
    off[t+1] = sh[t];
    if (!t) off[0] = 0;
}

// ---------------- CSR build ----------------
__global__ void k_deg(const int* __restrict__ dst, int E, int nloop, int* __restrict__ deg){
    int i = blockIdx.x*blockDim.x + threadIdx.x;
    int tot = E + nloop;
    if (i >= tot) return;
    int d = (i < E) ? dst[i] : (i - E);
    atomicAdd(&deg[d], 1);
}
__global__ void k_fill_csr(const int* __restrict__ src, const int* __restrict__ dst,
                           int E, int nloop,
                           int* __restrict__ cursor, int* __restrict__ csrc){
    int i = blockIdx.x*blockDim.x + threadIdx.x;
    int tot = E + nloop;
    if (i >= tot) return;
    int d, v;
    if (i < E){ d = dst[i]; v = src[i]; }
    else      { d = i - E;  v = d | 0x80000000; }
    int pos = atomicAdd(&cursor[d], 1);
    csrc[pos] = v;
}

// ---------------- w-tilde ----------------
__global__ void k_wtilde(const float* __restrict__ Wd, const float* __restrict__ ad_src,
                         const float* __restrict__ ad_dst,
                         const float* __restrict__ Wp, const float* __restrict__ ap_src,
                         const float* __restrict__ ap_dst,
                         const float* __restrict__ Wi_src, const float* __restrict__ ai_src,
                         const float* __restrict__ Wi_dst, const float* __restrict__ ai_dst,
                         float* __restrict__ wv){
    int d = threadIdx.x;
    if (d >= DD) return;
    const float* Ws[16]  = {Wd,Wd,Wd,Wd, Wi_dst,Wi_dst, Wi_src,Wi_src, Wp,Wp, Wp,Wp, Wi_dst,Wi_dst, Wi_src,Wi_src};
    const float* as[16]  = {ad_src,ad_src,ad_dst,ad_dst, ai_dst,ai_dst, ai_src,ai_src,
                            ap_src,ap_src, ap_dst,ap_dst, ai_dst,ai_dst, ai_src,ai_src};
    const int    hs[16]  = {0,1,0,1, 0,1, 0,1, 0,1, 0,1, 0,1, 0,1};
    for (int slot = 0; slot < 16; slot++){
        const float* W = Ws[slot]; const float* a = as[slot]; int h = hs[slot];
        float s = 0.f;
        for (int c = 0; c < 50; c++) s += W[d*HCC + h*50 + c]*a[h*50 + c];
        wv[slot*DD + d] = s;
    }
}

// ---------------- combined weights + transposed bf16 split W ----------------
__global__ void k_prepW2(const float* __restrict__ Wd, const float* __restrict__ Wp,
                         const float* __restrict__ Wi_src, const float* __restrict__ wv,
                         float* __restrict__ WcA1, float* __restrict__ WcA2,
                         __nv_bfloat16* __restrict__ WhT, __nv_bfloat16* __restrict__ WlT){
    int i = blockIdx.x*blockDim.x + threadIdx.x;
    const int S1 = 200*112;
    if (i < S1){
        int k = i/112, c = i%112;
        float v = 0.f;
        if (c < 100) v = Wd[k*HCC + c];
        else if (c < 106) v = wv[(c-100)*DD + k];
        WcA1[i] = v;
    } else if (i < 2*S1){
        int j = i - S1; int k = j/112, c = j%112;
        float v = 0.f;
        if (c < 100) v = Wi_src[k*HCC + c];
        else if (c < 102) v = wv[(14 + (c-100))*DD + k];
        WcA2[j] = v;
    } else if (i < 2*S1 + KPAD*KPAD){
        int j = i - 2*S1; int n = j / KPAD, k = j % KPAD;
        float v = 0.f;
        if (k < 200){
            if (n < 100) v = Wi_src[k*HCC + n];
            else if (n < 200) v = Wp[k*HCC + (n-100)];
            else v = wv[(6 + (n-200))*DD + k];
        }
        __nv_bfloat16 h = __float2bfloat16(v);
        float hv = __bfloat162float(h);
        WhT[j] = h;
        WlT[j] = __float2bfloat16(v - hv);
    }
}

// ---------------- X conversion ----------------
__global__ void k_cvt_x(const float* __restrict__ x,
                        __nv_bfloat16* __restrict__ hi, __nv_bfloat16* __restrict__ lo){
    long i = (long)blockIdx.x*blockDim.x + threadIdx.x;
    long tot = (long)NAA*KPAD;
    if (i >= tot) return;
    int col = (int)(i % KPAD);
    long row = i / KPAD;
    float v = 0.f;
    if (col < 200) v = eluf(x[row*DD + col]);
    __nv_bfloat16 h = __float2bfloat16(v);
    float hv = __bfloat162float(h);
    hi[i] = h;
    lo[i] = __float2bfloat16(v - hv);
}

// ---------------- HMMA dual GEMM v4 ----------------
#define WPITCH 216
#define SM_BYTES (2*KPAD*WPITCH*2)

#define MMA16816(d, a, b0, b1) \
    asm volatile("mma.sync.aligned.m16n8k16.row.col.f32.bf16.bf16.f32 " \
        "{%0,%1,%2,%3}, {%4,%5,%6,%7}, {%8,%9}, {%0,%1,%2,%3};" \
        : "+f"((d)[0]),"+f"((d)[1]),"+f"((d)[2]),"+f"((d)[3]) \
        : "r"((a)[0]),"r"((a)[1]),"r"((a)[2]),"r"((a)[3]), "r"(b0),"r"(b1))

__global__ __launch_bounds__(512,1)
void k_hmma(const __nv_bfloat16* __restrict__ Xhi, const __nv_bfloat16* __restrict__ Xlo,
            const __nv_bfloat16* __restrict__ Bhg, const __nv_bfloat16* __restrict__ Blg,
            float* __restrict__ O0, float* __restrict__ O1,
            float* __restrict__ dots, int twoN){
    extern __shared__ __nv_bfloat16 sm[];
    __nv_bfloat16* Wh = sm;
    __nv_bfloat16* Wl = sm + KPAD*WPITCH;
    int tid = threadIdx.x;
    int wid = tid >> 5, lane = tid & 31;
    int wm = wid & 7, wn = wid >> 3;
    int g = lane >> 2, tig = lane & 3;
    long row0 = (long)blockIdx.x * 128;

    for (int u = tid; u < KPAD*104; u += 512){
        int n = u / 104, kp = u % 104;
        *(unsigned*)&Wh[n*WPITCH + kp*2] = *(const unsigned*)(Bhg + (long)n*KPAD + kp*2);
        *(unsigned*)&Wl[n*WPITCH + kp*2] = *(const unsigned*)(Blg + (long)n*KPAD + kp*2);
    }
    __syncthreads();

    float acc[13][4];
    #pragma unroll
    for (int j = 0; j < 13; j++)
        #pragma unroll
        for (int q = 0; q < 4; q++) acc[j][q] = 0.f;

    long ar0 = (row0 + wm*16 + g)*KPAD + tig*2;
    long ar8 = ar0 + 8*KPAD;

    unsigned ah[4], al[4], pah[4], pal[4];
    pah[0] = *(const unsigned*)(Xhi + ar0);
    pah[1] = *(const unsigned*)(Xhi + ar8);
    pah[2] = *(const unsigned*)(Xhi + ar0 + 8);
    pah[3] = *(const unsigned*)(Xhi + ar8 + 8);
    pal[0] = *(const unsigned*)(Xlo + ar0);
    pal[1] = *(const unsigned*)(Xlo + ar8);
    pal[2] = *(const unsigned*)(Xlo + ar0 + 8);
    pal[3] = *(const unsigned*)(Xlo + ar8 + 8);

    for (int kc = 0; kc < 13; kc++){
        #pragma unroll
        for (int q = 0; q < 4; q++){ ah[q] = pah[q]; al[q] = pal[q]; }
        if (kc < 12){
            int k0 = (kc+1)*16;
            pah[0] = *(const unsigned*)(Xhi + ar0 + k0);
            pah[1] = *(const unsigned*)(Xhi + ar8 + k0);
            pah[2] = *(const unsigned*)(Xhi + ar0 + k0 + 8);
            pah[3] = *(const unsigned*)(Xhi + ar8 + k0 + 8);
            pal[0] = *(const unsigned*)(Xlo + ar0 + k0);
            pal[1] = *(const unsigned*)(Xlo + ar8 + k0);
            pal[2] = *(const unsigned*)(Xlo + ar0 + k0 + 8);
            pal[3] = *(const unsigned*)(Xlo + ar8 + k0 + 8);
        }
        int kb = kc*16 + tig*2;
        #pragma unroll
        for (int j = 0; j < 13; j++){
            int nrow = wn*104 + j*8 + g;
            const __nv_bfloat16* wph = &Wh[nrow*WPITCH + kb];
            const __nv_bfloat16* wpl = &Wl[nrow*WPITCH + kb];
            unsigned bh0 = *(const unsigned*)wph;
            unsigned bh1 = *(const unsigned*)(wph + 8);
            unsigned bl0 = *(const unsigned*)wpl;
            unsigned bl1 = *(const unsigned*)(wpl + 8);
            MMA16816(acc[j], ah, bh0, bh1);
            MMA16816(acc[j], ah, bl0, bl1);
            MMA16816(acc[j], al, bh0, bh1);
        }
    }

    long r_hi = row0 + wm*16 + g;
    long r_lo = r_hi + 8;
    #pragma unroll
    for (int j = 0; j < 13; j++){
        int colb = wn*104 + j*8 + tig*2;
        #pragma unroll
        for (int h = 0; h < 2; h++){
            long row = h ? r_lo : r_hi;
            float2 v = make_float2(acc[j][2*h], acc[j][2*h+1]);
            if (colb < 100)      *(float2*)&O0[row*HCC + colb] = v;
            else if (colb < 200) *(float2*)&O1[row*HCC + (colb-100)] = v;
            else {
                int pr = (colb - 200) >> 1;
                *(float2*)&dots[(long)pr*twoN + row*2] = v;
            }
        }
    }
}

// ---------------- GEMM v6 (fp32 FMA2, atom-side) ----------------
#define FMA2(acc, x, w) asm("fma.rn.f32x2 %0, %1, %2, %0;" : "+l"(acc) : "l"(x), "l"(w))
#define DUP2(dst, f)    asm("mov.b64 %0, {%1, %1};" : "=l"(dst) : "r"(__float_as_uint(f)))

template<int NW, int NOUT, int NDOT, bool ELU>
__global__ __launch_bounds__(NW*32, 2)
void k_gemm6(const float* __restrict__ X, const float* __restrict__ Wc,
             float* __restrict__ O0, float* __restrict__ O1,
             float* __restrict__ dots, int twoN){
    constexpr int NC = NW*16;
    constexpr int T  = NW*32;
    constexpr int NXF = (320 + T - 1)/T;
    constexpr int NWF = (20*NC + T - 1)/T;
    __shared__ __align__(16) float Xs[20][64];
    __shared__ __align__(16) float Ws[20*NC];
    int tid = threadIdx.x;
    int wi = tid >> 5, lane = tid & 31;
    long row0 = (long)blockIdx.x * 64;

    float4 xv[NXF];
    float wreg[NWF];

    #pragma unroll
    for (int i = 0; i < NXF; i++){
        int u = tid + i*T;
        if (u < 320){
            int r = u/5, q = u%5;
            float4 v = *(const float4*)&X[(row0+r)*DD + q*4];
            if (ELU){ v.x=eluf(v.x); v.y=eluf(v.y); v.z=eluf(v.z); v.w=eluf(v.w); }
            xv[i] = v;
        }
    }
    #pragma unroll
    for (int i = 0; i < NWF; i++){
        int u = tid + i*T;
        if (u < 20*NC) wreg[i] = Wc[u];
    }

    ull acc[2][8];
    #pragma unroll
    for (int r = 0; r < 2; r++)
        #pragma unroll
        for (int j = 0; j < 8; j++) acc[r][j] = 0ull;

    for (int it = 0; it < 10; it++){
        if (it) __syncthreads();
        #pragma unroll
        for (int i = 0; i < NXF; i++){
            int u = tid + i*T;
            if (u < 320){
                int r = u/5, q = u%5;
                #pragma unroll
                for (int j = 0; j < 4; j++)
                    Xs[q*4+j][r] = ((const float*)&xv[i])[j];
            }
        }
        #pragma unroll
        for (int i = 0; i < NWF; i++){
            int u = tid + i*T;
            if (u < 20*NC) Ws[u] = wreg[i];
        }
        __syncthreads();
        if (it < 9){
            int k0n = (it+1)*20;
            #pragma unroll
            for (int i = 0; i < NXF; i++){
                int u = tid + i*T;
                if (u < 320){
                    int r = u/5, q = u%5;
                    float4 v = *(const float4*)&X[(row0+r)*DD + k0n + q*4];
                    if (ELU){ v.x=eluf(v.x); v.y=eluf(v.y); v.z=eluf(v.z); v.w=eluf(v.w); }
                    xv[i] = v;
                }
            }
            #pragma unroll
            for (int i = 0; i < NWF; i++){
                int u = tid + i*T;
                if (u < 20*NC) wreg[i] = Wc[k0n*NC + u];
            }
        }
        #pragma unroll 5
        for (int k = 0; k < 20; k++){
            float2 x2 = *(const float2*)&Xs[k][2*lane];
            ull xlo, xhi;
            DUP2(xlo, x2.x);
            DUP2(xhi, x2.y);
            const ulonglong2* wp = (const ulonglong2*)&Ws[k*NC + wi*16];
            ulonglong2 wA = wp[0], wB = wp[1], wC = wp[2], wD = wp[3];
            ull wc8[8] = {wA.x, wA.y, wB.x, wB.y, wC.x, wC.y, wD.x, wD.y};
            #pragma unroll
            for (int j = 0; j < 8; j++){
                FMA2(acc[0][j], xlo, wc8[j]);
                FMA2(acc[1][j], xhi, wc8[j]);
            }
        }
    }

    #pragma unroll
    for (int j = 0; j < 8; j++){
        int col = wi*16 + 2*j;
        long r0 = row0 + 2*lane;
        if (col < 100){
            *(ull*)&O0[r0*HCC + col]     = acc[0][j];
            *(ull*)&O0[(r0+1)*HCC + col] = acc[1][j];
        } else if (NOUT == 2 && col < 200){
            *(ull*)&O1[r0*HCC + (col-100)]     = acc[0][j];
            *(ull*)&O1[(r0+1)*HCC + (col-100)] = acc[1][j];
        } else if (col >= 100*NOUT && col < 100*NOUT + NDOT){
            int pr = (col - 100*NOUT) >> 1;
            *(ull*)&dots[(long)pr*twoN + r0*2]     = acc[0][j];
            *(ull*)&dots[(long)pr*twoN + (r0+1)*2] = acc[1][j];
        }
    }
}

// ---------------- fused GAT aggregation + LN stats (unrolled x2, __expf) ----------------
__global__ void k_gat_node(const int* __restrict__ rowptr, const int* __restrict__ csrc,
                           const float* __restrict__ hs,
                           const float* __restrict__ als, const float* __restrict__ ald,
                           const float* __restrict__ bias, const int* __restrict__ batch,
                           float* __restrict__ stats,
                           float* __restrict__ out, int coloff, int n){
    int w = (blockIdx.x*blockDim.x + threadIdx.x) >> 5;
    int lane = threadIdx.x & 31;
    if (w >= n) return;
    float2 aldv = *(const float2*)&ald[2*w];
    int beg = rowptr[w], end = rowptr[w+1];
    float a0 = 0.f, a1 = 0.f, a2 = 0.f, a3 = 0.f, z0 = 0.f, z1 = 0.f;
    int j = beg;
    for (; j + 2 <= end; j += 2){
        int s0 = csrc[j]   & 0x7fffffff;
        int s1 = csrc[j+1] & 0x7fffffff;
        float2 A0 = *(const float2*)&als[2*s0];
        float2 A1 = *(const float2*)&als[2*s1];
        const float* h0 = hs + (long)s0*HCC;
        const float* h1 = hs + (long)s1*HCC;
        float u00 = h0[lane], u01 = h0[lane+32], u02 = h0[lane+64];
        float u10 = h1[lane], u11 = h1[lane+32], u12 = h1[lane+64];
        float u03 = (lane < 4) ? h0[lane+96] : 0.f;
        float u13 = (lane < 4) ? h1[lane+96] : 0.f;
        float l00 = A0.x + aldv.x, l01 = A0.y + aldv.y;
        float l10 = A1.x + aldv.x, l11 = A1.y + aldv.y;
        l00 = l00 > 0.f ? l00 : 0.2f*l00;
        l01 = l01 > 0.f ? l01 : 0.2f*l01;
        l10 = l10 > 0.f ? l10 : 0.2f*l10;
        l11 = l11 > 0.f ? l11 : 0.2f*l11;
        float e00 = __expf(l00), e01 = __expf(l01);
        float e10 = __expf(l10), e11 = __expf(l11);
        z0 += e00 + e10; z1 += e01 + e11;
        a0 += e00*u00 + e10*u10;
        float w0m = (lane < 18) ? e00 : e01;
        float w1m = (lane < 18) ? e10 : e11;
        a1 += w0m*u01 + w1m*u11;
        a2 += e01*u02 + e11*u12;
        a3 += e01*u03 + e11*u13;
    }
    if (j < end){
        int s = csrc[j] & 0x7fffffff;
        float2 A = *(const float2*)&als[2*s];
        const float* h = hs + (long)s*HCC;
        float l0 = A.x + aldv.x, l1 = A.y + aldv.y;
        l0 = l0 > 0.f ? l0 : 0.2f*l0;
        l1 = l1 > 0.f ? l1 : 0.2f*l1;
        float e0 = __expf(l0), e1 = __expf(l1);
        z0 += e0; z1 += e1;
        a0 += e0*h[lane];
        a1 += ((lane < 18) ? e0 : e1)*h[lane+32];
        a2 += e1*h[lane+64];
        if (lane < 4) a3 += e1*h[lane+96];
    }
    float iz0 = 1.f/(z0 + 1e-16f), iz1 = 1.f/(z1 + 1e-16f);
    float o0 = bias[lane]    + a0*iz0;
    float o1 = bias[lane+32] + a1*(lane < 18 ? iz0 : iz1);
    float o2 = bias[lane+64] + a2*iz1;
    float o3 = (lane < 4) ? (bias[lane+96] + a3*iz1) : 0.f;
    float* o = out + (long)w*DD + coloff;
    o[lane]    = o0;
    o[lane+32] = o1;
    o[lane+64] = o2;
    if (lane < 4) o[lane+96] = o3;
    float s  = o0 + o1 + o2 + o3;
    float s2 = o0*o0 + o1*o1 + o2*o2 + o3*o3;
    #pragma unroll
    for (int off = 16; off > 0; off >>= 1){
        s  += __shfl_down_sync(0xffffffffu, s,  off);
        s2 += __shfl_down_sync(0xffffffffu, s2, off);
    }
    if (!lane){
        int b = batch[w];
        atomicAdd(&stats[2*b],   s);
        atomicAdd(&stats[2*b+1], s2);
    }
}

// ---------------- warp-per-row LN apply + ELU + fused SAG dots ----------------
__global__ void k_ln_pool(const float* __restrict__ x, const int* __restrict__ batch,
                          const int* __restrict__ goff, const float* __restrict__ stats,
                          const float* __restrict__ w, const float* __restrict__ bia,
                          const float* __restrict__ wrel, const float* __restrict__ wroot,
                          float* __restrict__ y, float* __restrict__ t1,
                          float* __restrict__ t2, int n){
    __shared__ float sw[DD], sb[DD], sr[DD], so[DD];
    for (int i = threadIdx.x; i < DD; i += blockDim.x){
        sw[i] = w[i]; sb[i] = bia[i]; sr[i] = wrel[i]; so[i] = wroot[i];
    }
    __syncthreads();
    int row = (blockIdx.x*blockDim.x + threadIdx.x) >> 5;
    int lane = threadIdx.x & 31;
    if (row >= n) return;
    int b = batch[row];
    float cnt = (float)(goff[b+1] - goff[b]);
    float norm = fmaxf(cnt, 1.f) * (float)DD;
    float mean = stats[2*b] / norm;
    float var  = stats[2*b+1] / norm - mean*mean;
    float rs   = rsqrtf(fmaxf(var, 0.f) + 1e-5f);
    const float* xr = x + (long)row*DD;
    float* yr = y + (long)row*DD;
    float a = 0.f, bb = 0.f;
    #pragma unroll
    for (int c = lane; c < DD; c += 32){
        float v = eluf((xr[c] - mean)*rs*sw[c] + sb[c]);
        yr[c] = v;
        a  += v*sr[c];
        bb += v*so[c];
    }
    #pragma unroll
    for (int off = 16; off > 0; off >>= 1){
        a  += __shfl_down_sync(0xffffffffu, a,  off);
        bb += __shfl_down_sync(0xffffffffu, bb, off);
    }
    if (!lane){ t1[row] = a; t2[row] = bb; }
}

// ---------------- SAG pooling ----------------
__global__ void k_sagg_csr(const int* __restrict__ rowptr, const int* __restrict__ csrc,
                           const float* __restrict__ t1, float* __restrict__ sagg, int n){
    int i = blockIdx.x*blockDim.x + threadIdx.x;
    if (i >= n) return;
    float s = 0.f;
    int beg = rowptr[i], end = rowptr[i+1];
    for (int j = beg; j < end; j++){
        int v = csrc[j];
        if (v >= 0) s += t1[v];
    }
    sagg[i] = s;
}
__global__ void k_score_g(const float* __restrict__ sagg, const float* __restrict__ t2,
                          const float* __restrict__ brel, const int* __restrict__ goff,
                          float* __restrict__ e, float* __restrict__ ssum){
    int g = blockIdx.x;
    int beg = goff[g], end = goff[g+1];
    int t = threadIdx.x;
    float b0 = brel[0];
    __shared__ float red[256];
    float m = -3.4e38f;
    for (int r = beg + t; r < end; r += 256)
        m = fmaxf(m, sagg[r] + b0 + t2[r]);
    red[t] = m;
    __syncthreads();
    for (int off = 128; off > 0; off >>= 1){
        if (t < off) red[t] = fmaxf(red[t], red[t+off]);
        __syncthreads();
    }
    m = red[0];
    __syncthreads();
    float s = 0.f;
    for (int r = beg + t; r < end; r += 256){
        float v = __expf(sagg[r] + b0 + t2[r] - m);
        e[r] = v; s += v;
    }
    red[t] = s;
    __syncthreads();
    for (int off = 128; off > 0; off >>= 1){
        if (t < off) red[t] += red[t+off];
        __syncthreads();
    }
    if (!t) ssum[g] = red[0];
}
__global__ void k_final_chunk(const float* __restrict__ x, const int* __restrict__ batch,
                              const float* __restrict__ e, const float* __restrict__ ssum,
                              float* __restrict__ out, float* __restrict__ gsum, int n){
    int c = threadIdx.x;
    int r0 = blockIdx.x*64;
    int r1 = min(r0 + 64, n);
    int gcur = batch[r0];
    float inv = 1.f/(ssum[gcur] + 1e-16f);
    float acc = 0.f;
    for (int r = r0; r < r1; r++){
        int g = batch[r];
        if (g != gcur){
            atomicAdd(&gsum[gcur*DD + c], acc);
            acc = 0.f; gcur = g;
            inv = 1.f/(ssum[g] + 1e-16f);
        }
        float sc = e[r]*inv;
        float v = x[(long)r*DD + c]*sc;
        out[(long)r*DD + c] = v;
        acc += v;
    }
    atomicAdd(&gsum[gcur*DD + c], acc);
}

// ---------------- host ----------------
static void* symaddr(const void* s){ void* p = nullptr; cudaGetSymbolAddress(&p, s); return p; }

static void build_csr(const int* src, const int* dst, int E, int nloop, int n,
                      int* deg, int* part, int* rowptr, int* csrc, cudaStream_t st){
    int nb = CDIV(n, 512);
    k_fill_int<<<CDIV(n,256),256,0,st>>>(deg, n, 0);
    k_deg<<<CDIV(E+nloop,256),256,0,st>>>(dst, E, nloop, deg);
    k_scan_part<<<nb,512,0,st>>>(deg, n, part);
    k_scan_mid<<<1,512,0,st>>>(part, nb);
    k_scan_final<<<nb,512,0,st>>>(deg, part, n, rowptr, deg);
    k_fill_csr<<<CDIV(E+nloop,256),256,0,st>>>(src, dst, E, nloop, deg, csrc);
}

extern "C" void kernel_launch(void* const* d_in, const int* in_sizes, int n_in,
                              void* d_out, int out_size){
    const float* atom_x    = (const float*)d_in[0];
    const int*   atom_ei   = (const int*)  d_in[1];
    const int*   atom_batch= (const int*)  d_in[2];
    const float* aa_x      = (const float*)d_in[3];
    const int*   aa_ei     = (const int*)  d_in[4];
    const int*   aa_batch  = (const int*)  d_in[6];
    const int*   m2p       = (const int*)  d_in[7];
    const float* Wd     = (const float*)d_in[8];
    const float* ad_src = (const float*)d_in[9];
    const float* ad_dst = (const float*)d_in[10];
    const float* bd     = (const float*)d_in[11];
    const float* Wp     = (const float*)d_in[12];
    const float* ap_src = (const float*)d_in[13];
    const float* ap_dst = (const float*)d_in[14];
    const float* bp     = (const float*)d_in[15];
    const float* Wi_src = (const float*)d_in[16];
    const float* Wi_dst = (const float*)d_in[17];
    const float* ai_src = (const float*)d_in[18];
    const float* ai_dst = (const float*)d_in[19];
    const float* bi     = (const float*)d_in[20];
    const float* ln_d_w = (const float*)d_in[21];
    const float* ln_d_b = (const float*)d_in[22];
    const float* ln_p_w = (const float*)d_in[23];
    const float* ln_p_b = (const float*)d_in[24];
    const float* pd_Wrel  = (const float*)d_in[25];
    const float* pd_brel  = (const float*)d_in[26];
    const float* pd_Wroot = (const float*)d_in[27];
    const float* pp_Wrel  = (const float*)d_in[28];
    const float* pp_brel  = (const float*)d_in[29];
    const float* pp_Wroot = (const float*)d_in[30];

    float* hA     = (float*)symaddr(g_hA);
    float* hB     = (float*)symaddr(g_hB);
    float* hC     = (float*)symaddr(g_hC);
    float* cat_a  = (float*)symaddr(g_cat_atom);
    float* cat_p  = (float*)symaddr(g_cat_aa);
    float* atom_h = (float*)symaddr(g_atom_h);
    float* wv     = (float*)symaddr(g_wv);
    float* WcA1   = (float*)symaddr(g_WcA1);
    float* WcA2   = (float*)symaddr(g_WcA2);
    __nv_bfloat16* Xhi = (__nv_bfloat16*)symaddr(g_Xhi);
    __nv_bfloat16* Xlo = (__nv_bfloat16*)symaddr(g_Xlo);
    __nv_bfloat16* WhT = (__nv_bfloat16*)symaddr(g_WhT);
    __nv_bfloat16* WlT = (__nv_bfloat16*)symaddr(g_WlT);
    float* dotA   = (float*)symaddr(g_dotA);
    float* dotP   = (float*)symaddr(g_dotP);
    float* dotH   = (float*)symaddr(g_dotH);
    float* stats  = (float*)symaddr(g_stats);
    float* ta1    = (float*)symaddr(g_ta1);
    float* ta2    = (float*)symaddr(g_ta2);
    float* tp1    = (float*)symaddr(g_tp1);
    float* tp2    = (float*)symaddr(g_tp2);
    float* sagg   = (float*)symaddr(g_sagg);
    float* esc    = (float*)symaddr(g_esc);
    float* ssum   = (float*)symaddr(g_ssum);
    int* rowptr_a = (int*)symaddr(g_rowptr_a);
    int* csrc_a   = (int*)symaddr(g_csrc_a);
    int* rowptr_p = (int*)symaddr(g_rowptr_p);
    int* csrc_p   = (int*)symaddr(g_csrc_p);
    int* rowptr_m = (int*)symaddr(g_rowptr_m);
    int* csrc_m   = (int*)symaddr(g_csrc_m);
    int* rowptr_m2= (int*)symaddr(g_rowptr_m2);
    int* csrc_m2  = (int*)symaddr(g_csrc_m2);
    int* deg      = (int*)symaddr(g_deg);
    int* part     = (int*)symaddr(g_part);
    int* goff_a   = (int*)symaddr(g_goff_a);
    int* goff_p   = (int*)symaddr(g_goff_p);

    float* out      = (float*)d_out;
    float* out_atom = out + OUT_ATOM_OFF;
    float* out_aa   = out + OUT_AA_OFF;
    float* out_drug = out + OUT_DRUG_OFF;
    float* out_prot = out + OUT_PROT_OFF;

    const int BS = 256;
    const int* atom_src = atom_ei;  const int* atom_dst = atom_ei + EATOM;
    const int* aa_src   = aa_ei;    const int* aa_dst   = aa_ei + EAA;
    const int* m2p_at   = m2p;      const int* m2p_aa   = m2p + EM2P;

    static cudaStream_t s1 = nullptr;
    static cudaEvent_t evFork = nullptr, evJoin = nullptr;
    if (!s1){
        cudaStreamCreateWithFlags(&s1, cudaStreamNonBlocking);
        cudaEventCreateWithFlags(&evFork, cudaEventDisableTiming);
        cudaEventCreateWithFlags(&evJoin, cudaEventDisableTiming);
    }
    cudaFuncSetAttribute(k_hmma, cudaFuncAttributeMaxDynamicSharedMemorySize, SM_BYTES);

    // ---- fork: index pipeline on s1 ----
    cudaEventRecord(evFork, 0);
    cudaStreamWaitEvent(s1, evFork, 0);

    k_fill_int<<<CDIV(NG,BS),BS,0,s1>>>(deg, NG, 0);
    k_deg<<<CDIV(NATOM,BS),BS,0,s1>>>(atom_batch, NATOM, 0, deg);
    k_scan512<<<1,NG,0,s1>>>(deg, goff_a);
    k_fill_int<<<CDIV(NG,BS),BS,0,s1>>>(deg, NG, 0);
    k_deg<<<CDIV(NAA,BS),BS,0,s1>>>(aa_batch, NAA, 0, deg);
    k_scan512<<<1,NG,0,s1>>>(deg, goff_p);
    build_csr(atom_src, atom_dst, EATOM, NATOM, NATOM, deg, part, rowptr_a, csrc_a, s1);
    build_csr(aa_src,   aa_dst,   EAA,   NAA,   NAA,   deg, part, rowptr_p, csrc_p, s1);
    build_csr(m2p_aa,   m2p_at,   EM2P,  NATOM, NATOM, deg, part, rowptr_m, csrc_m, s1);
    build_csr(m2p_at,   m2p_aa,   EM2P,  NATOM, NAA,   deg, part, rowptr_m2, csrc_m2, s1);
    k_fill_f<<<CDIV(NG*DD,BS),BS,0,s1>>>(out_drug, NG*DD);
    k_fill_f<<<CDIV(NG*DD,BS),BS,0,s1>>>(out_prot, NG*DD);
    cudaEventRecord(evJoin, s1);

    // ---- main stream: compute pipeline ----
    k_wtilde<<<1,224>>>(Wd, ad_src, ad_dst, Wp, ap_src, ap_dst,
                        Wi_src, ai_src, Wi_dst, ai_dst, wv);
    k_prepW2<<<CDIV(2*200*112 + KPAD*KPAD, BS),BS>>>(Wd, Wp, Wi_src, wv, WcA1, WcA2, WhT, WlT);
    k_cvt_x<<<CDIV((long)NAA*KPAD, BS),BS>>>(aa_x, Xhi, Xlo);
    k_hmma<<<NAA/128, 512, SM_BYTES>>>(Xhi, Xlo, WhT, WlT, hA, hB, dotP, 2*NAA);
    k_gemm6<7,1,6,true><<<NATOM/64,224>>>(atom_x, WcA1, hC, nullptr, dotA, 2*NATOM);

    // ---- join ----
    cudaStreamWaitEvent(0, evJoin, 0);

    // GAT1 + GAT2 + fused LN stats -> cat_a
    k_fill_f<<<CDIV(NG*2,BS),BS>>>(stats, NG*2);
    k_gat_node<<<CDIV(NATOM*32,BS),BS>>>(rowptr_a, csrc_a, hC,
                                         dotA, dotA + 2*NATOM, bd, atom_batch, stats, cat_a, 0, NATOM);
    k_gat_node<<<CDIV(NATOM*32,BS),BS>>>(rowptr_m, csrc_m, hA,
                                         dotP, dotA + 4*NATOM, bi, atom_batch, stats, cat_a, HCC, NATOM);
    k_ln_pool<<<CDIV(NATOM*32,BS),BS>>>(cat_a, atom_batch, goff_a, stats,
                                        ln_d_w, ln_d_b, pd_Wrel, pd_Wroot,
                                        atom_h, ta1, ta2, NATOM);

    // layer 2
    k_gemm6<7,1,2,false><<<NATOM/64,224>>>(atom_h, WcA2, hC, nullptr, dotH, 2*NATOM);

    k_fill_f<<<CDIV(NG*2,BS),BS>>>(stats, NG*2);
    k_gat_node<<<CDIV(NAA*32,BS),BS>>>(rowptr_p, csrc_p, hB,
                                       dotP + 2*NAA, dotP + 4*NAA, bp, aa_batch, stats, cat_p, 0, NAA);
    k_gat_node<<<CDIV(NAA*32,BS),BS>>>(rowptr_m2, csrc_m2, hC,
                                       dotH, dotP + 6*NAA, bi, aa_batch, stats, cat_p, HCC, NAA);
    k_ln_pool<<<CDIV(NAA*32,BS),BS>>>(cat_p, aa_batch, goff_p, stats,
                                      ln_p_w, ln_p_b, pp_Wrel, pp_Wroot,
                                      out_aa, tp1, tp2, NAA);

    // SAG pool (atoms) + drug_g
    k_sagg_csr<<<CDIV(NATOM,BS),BS>>>(rowptr_a, csrc_a, ta1, sagg, NATOM);
    k_score_g<<<NG,256>>>(sagg, ta2, pd_brel, goff_a, esc, ssum);
    k_final_chunk<<<CDIV(NATOM,64),DD>>>(atom_h, atom_batch, esc, ssum, out_atom, out_drug, NATOM);

    // SAG pool (aa) + prot_g
    k_sagg_csr<<<CDIV(NAA,BS),BS>>>(rowptr_p, csrc_p, tp1, sagg, NAA);
    k_score_g<<<NG,256>>>(sagg, tp2, pp_brel, goff_p, esc, ssum);
    k_final_chunk<<<CDIV(NAA,64),DD>>>(out_aa, aa_batch, esc, ssum, out_aa, out_prot, NAA);
}